// round 1
// baseline (speedup 1.0000x reference)
#include <cuda_runtime.h>
#include <cuda_bf16.h>
#include <math.h>

// ---------------------------------------------------------------------------
// Problem constants
// ---------------------------------------------------------------------------
#define BATCH   4
#define SEQL    2048
#define DMODEL  256
#define DINNER  512
#define NSTATE  16
#define DCONV   4
#define NTOK    (BATCH * SEQL)          // 8192
#define RMS_EPS 1.1920929e-07f

#define NCH     16                       // scan chunks
#define CT      (SEQL / NCH)             // 128 steps per chunk

#define NDBC    640                      // padded N for fused delta/B/C gemm (544 real)

// ---------------------------------------------------------------------------
// Scratch (static device globals; no allocation allowed)
// ---------------------------------------------------------------------------
__device__ float g_xn   [(size_t)NTOK * DMODEL];        // rmsnorm output
__device__ float g_xz   [(size_t)NTOK * 2 * DINNER];    // in_proj out: x_branch | z
__device__ float g_xc   [(size_t)NTOK * DINNER];        // conv + silu
__device__ float g_delta[(size_t)NTOK * DINNER];        // softplus(delta)
__device__ float g_BC   [(size_t)NTOK * 32];            // B_t (16) | C_t (16)
__device__ float g_Wdbc [(size_t)NDBC * DINNER];        // concat(projDelta_w, projB_w, projC_w, zeros)
__device__ float g_P    [(size_t)BATCH * NCH * NSTATE * DINNER];
__device__ float g_S    [(size_t)BATCH * NCH * NSTATE * DINNER];
__device__ float g_H    [(size_t)BATCH * NCH * NSTATE * DINNER];
__device__ float g_y    [(size_t)NTOK * DINNER];

// ---------------------------------------------------------------------------
// Helpers
// ---------------------------------------------------------------------------
__device__ __forceinline__ float silu_f(float v) {
    return v / (1.0f + __expf(-v));
}
__device__ __forceinline__ float softplus_f(float v) {
    return (v > 20.0f) ? v : log1pf(__expf(v));
}

// ---------------------------------------------------------------------------
// RMSNorm: one block per token
// ---------------------------------------------------------------------------
__global__ void rmsnorm_kernel(const float* __restrict__ x,
                               const float* __restrict__ w,
                               float* __restrict__ xn) {
    int t = blockIdx.x;
    int i = threadIdx.x;                 // 0..255
    float v = x[(size_t)t * DMODEL + i];
    float ss = v * v;
    #pragma unroll
    for (int o = 16; o; o >>= 1) ss += __shfl_xor_sync(0xFFFFFFFFu, ss, o);
    __shared__ float red[8];
    if ((i & 31) == 0) red[i >> 5] = ss;
    __syncthreads();
    float tot = 0.f;
    #pragma unroll
    for (int j = 0; j < 8; j++) tot += red[j];
    float scale = rsqrtf(tot * (1.0f / DMODEL) + RMS_EPS);
    xn[(size_t)t * DMODEL + i] = v * scale * w[i];
}

// ---------------------------------------------------------------------------
// Concatenate projDelta_w / projB_w / projC_w into one padded weight matrix
// ---------------------------------------------------------------------------
__global__ void concat_w_kernel(const float* __restrict__ wd,
                                const float* __restrict__ wb,
                                const float* __restrict__ wc) {
    int idx = blockIdx.x * blockDim.x + threadIdx.x;   // over NDBC*DINNER
    if (idx >= NDBC * DINNER) return;
    int r = idx / DINNER;
    int k = idx - r * DINNER;
    float v;
    if      (r < 512) v = wd[(size_t)r * DINNER + k];
    else if (r < 528) v = wb[(size_t)(r - 512) * DINNER + k];
    else if (r < 544) v = wc[(size_t)(r - 528) * DINNER + k];
    else              v = 0.0f;
    g_Wdbc[idx] = v;
}

// ---------------------------------------------------------------------------
// Tiled fp32 GEMM, C[M,N] = A[M,K] * W[N,K]^T  (both K-contiguous, "NT")
// BM=BN=128, BK=16, 256 threads, 8x8 microtile. Fused epilogues by EPI.
//  EPI 0: plain store to C (ld = N)                      -> in_proj
//  EPI 1: j<512: softplus(acc+bias[j]) -> g_delta[t][j]
//         512<=j<544: g_BC[t][j-512]                     -> delta/B/C
//  EPI 2: acc + resid[t][j] -> C (ld = N)                -> out_proj
// ---------------------------------------------------------------------------
#define GBM 128
#define GBN 128
#define GBK 16

template<int EPI>
__global__ __launch_bounds__(256, 2)
void gemm_nt(const float* __restrict__ A, const float* __restrict__ W,
             float* __restrict__ C, int M, int N, int K,
             const float* __restrict__ bias,
             const float* __restrict__ resid) {
    __shared__ float As[GBK][GBM + 4];
    __shared__ float Bs[GBK][GBN + 4];

    int tid = threadIdx.x;
    int m0 = blockIdx.y * GBM;
    int n0 = blockIdx.x * GBN;
    int tx = tid & 15;        // col group
    int ty = tid >> 4;        // row group

    float acc[8][8];
    #pragma unroll
    for (int i = 0; i < 8; i++)
        #pragma unroll
        for (int j = 0; j < 8; j++) acc[i][j] = 0.0f;

    for (int k0 = 0; k0 < K; k0 += GBK) {
        #pragma unroll
        for (int i = 0; i < 2; i++) {
            int idx = tid + i * 256;          // 0..511 float4 slots
            int r = idx >> 2;                 // 0..127
            int c = (idx & 3) * 4;            // 0,4,8,12
            float4 v = *(const float4*)(A + (size_t)(m0 + r) * K + k0 + c);
            As[c + 0][r] = v.x; As[c + 1][r] = v.y;
            As[c + 2][r] = v.z; As[c + 3][r] = v.w;
        }
        #pragma unroll
        for (int i = 0; i < 2; i++) {
            int idx = tid + i * 256;
            int r = idx >> 2;
            int c = (idx & 3) * 4;
            float4 v = *(const float4*)(W + (size_t)(n0 + r) * K + k0 + c);
            Bs[c + 0][r] = v.x; Bs[c + 1][r] = v.y;
            Bs[c + 2][r] = v.z; Bs[c + 3][r] = v.w;
        }
        __syncthreads();

        #pragma unroll
        for (int k = 0; k < GBK; k++) {
            float4 a0 = *(const float4*)&As[k][ty * 8];
            float4 a1 = *(const float4*)&As[k][ty * 8 + 4];
            float4 b0 = *(const float4*)&Bs[k][tx * 8];
            float4 b1 = *(const float4*)&Bs[k][tx * 8 + 4];
            float av[8] = {a0.x, a0.y, a0.z, a0.w, a1.x, a1.y, a1.z, a1.w};
            float bv[8] = {b0.x, b0.y, b0.z, b0.w, b1.x, b1.y, b1.z, b1.w};
            #pragma unroll
            for (int i = 0; i < 8; i++)
                #pragma unroll
                for (int j = 0; j < 8; j++)
                    acc[i][j] = fmaf(av[i], bv[j], acc[i][j]);
        }
        __syncthreads();
    }

    #pragma unroll
    for (int i = 0; i < 8; i++) {
        int t = m0 + ty * 8 + i;
        #pragma unroll
        for (int j = 0; j < 8; j++) {
            int n = n0 + tx * 8 + j;
            float v = acc[i][j];
            if (EPI == 0) {
                C[(size_t)t * N + n] = v;
            } else if (EPI == 1) {
                if (n < 512) {
                    g_delta[(size_t)t * DINNER + n] = softplus_f(v + bias[n]);
                } else if (n < 544) {
                    g_BC[(size_t)t * 32 + (n - 512)] = v;
                }
            } else { // EPI == 2
                C[(size_t)t * N + n] = v + resid[(size_t)t * N + n];
            }
        }
    }
}

// ---------------------------------------------------------------------------
// Causal depthwise conv (width 4) + bias + SiLU.  Reads x_branch from g_xz.
// ---------------------------------------------------------------------------
__global__ void conv_silu_kernel(const float* __restrict__ cw,
                                 const float* __restrict__ cb) {
    int idx = blockIdx.x * blockDim.x + threadIdx.x;   // t*512 + d
    if (idx >= NTOK * DINNER) return;
    int t = idx >> 9;
    int d = idx & 511;
    int l = t & (SEQL - 1);
    float acc = cb[d];
    #pragma unroll
    for (int i = 0; i < DCONV; i++) {
        int li = l - (DCONV - 1) + i;
        if (li >= 0)
            acc = fmaf(cw[d * DCONV + i],
                       g_xz[(size_t)(t - (DCONV - 1) + i) * (2 * DINNER) + d], acc);
    }
    g_xc[idx] = silu_f(acc);
}

// ---------------------------------------------------------------------------
// Scan pass A: per-chunk decay product P and zero-init end state S.
// grid (DINNER/128, NCH, BATCH), 128 threads; thread owns (b, chunk, d).
// ---------------------------------------------------------------------------
__global__ void scan_phaseA(const float* __restrict__ A_log) {
    int d = blockIdx.x * 128 + threadIdx.x;
    int c = blockIdx.y;
    int b = blockIdx.z;

    float A2[NSTATE], h[NSTATE], p[NSTATE];
    #pragma unroll
    for (int n = 0; n < NSTATE; n++) {
        A2[n] = -__expf(A_log[d * NSTATE + n]) * 1.4426950408889634f;
        h[n] = 0.0f;
        p[n] = 1.0f;
    }
    int tbase = b * SEQL + c * CT;
    for (int s = 0; s < CT; s++) {
        int t = tbase + s;
        float dl = g_delta[(size_t)t * DINNER + d];
        float xv = g_xc  [(size_t)t * DINNER + d];
        float xd = xv * dl;
        const float4* bc = (const float4*)(g_BC + (size_t)t * 32);
        float4 b0 = bc[0], b1 = bc[1], b2 = bc[2], b3 = bc[3];
        float bvals[NSTATE] = {b0.x,b0.y,b0.z,b0.w, b1.x,b1.y,b1.z,b1.w,
                               b2.x,b2.y,b2.z,b2.w, b3.x,b3.y,b3.z,b3.w};
        #pragma unroll
        for (int n = 0; n < NSTATE; n++) {
            float dA = exp2f(dl * A2[n]);
            h[n] = fmaf(dA, h[n], xd * bvals[n]);
            p[n] *= dA;
        }
    }
    size_t base = (((size_t)b * NCH + c) * NSTATE) * DINNER + d;
    #pragma unroll
    for (int n = 0; n < NSTATE; n++) {
        g_P[base + (size_t)n * DINNER] = p[n];
        g_S[base + (size_t)n * DINNER] = h[n];
    }
}

// ---------------------------------------------------------------------------
// Scan pass B: sequential carry across chunks (tiny).
// One thread per (b, n, d) = 32768 threads.
// ---------------------------------------------------------------------------
__global__ void scan_phaseB() {
    int idx = blockIdx.x * blockDim.x + threadIdx.x;
    if (idx >= BATCH * NSTATE * DINNER) return;
    int d = idx & 511;
    int n = (idx >> 9) & 15;
    int b = idx >> 13;
    float h = 0.0f;
    for (int c = 0; c < NCH; c++) {
        size_t o = (((size_t)b * NCH + c) * NSTATE + n) * DINNER + d;
        g_H[o] = h;
        h = fmaf(g_P[o], h, g_S[o]);
    }
}

// ---------------------------------------------------------------------------
// Scan pass C: rerun chunk with true initial state; fused +x*D, *silu(z).
// ---------------------------------------------------------------------------
__global__ void scan_phaseC(const float* __restrict__ A_log,
                            const float* __restrict__ Dw) {
    int d = blockIdx.x * 128 + threadIdx.x;
    int c = blockIdx.y;
    int b = blockIdx.z;

    float A2[NSTATE], h[NSTATE];
    size_t hbase = (((size_t)b * NCH + c) * NSTATE) * DINNER + d;
    #pragma unroll
    for (int n = 0; n < NSTATE; n++) {
        A2[n] = -__expf(A_log[d * NSTATE + n]) * 1.4426950408889634f;
        h[n] = g_H[hbase + (size_t)n * DINNER];
    }
    float Dd = Dw[d];
    int tbase = b * SEQL + c * CT;
    for (int s = 0; s < CT; s++) {
        int t = tbase + s;
        float dl = g_delta[(size_t)t * DINNER + d];
        float xv = g_xc  [(size_t)t * DINNER + d];
        float xd = xv * dl;
        const float4* bc = (const float4*)(g_BC + (size_t)t * 32);
        float4 b0 = bc[0], b1 = bc[1], b2 = bc[2], b3 = bc[3];
        float4 c0 = bc[4], c1 = bc[5], c2 = bc[6], c3 = bc[7];
        float bvals[NSTATE] = {b0.x,b0.y,b0.z,b0.w, b1.x,b1.y,b1.z,b1.w,
                               b2.x,b2.y,b2.z,b2.w, b3.x,b3.y,b3.z,b3.w};
        float cvals[NSTATE] = {c0.x,c0.y,c0.z,c0.w, c1.x,c1.y,c1.z,c1.w,
                               c2.x,c2.y,c2.z,c2.w, c3.x,c3.y,c3.z,c3.w};
        float yv = 0.0f;
        #pragma unroll
        for (int n = 0; n < NSTATE; n++) {
            float dA = exp2f(dl * A2[n]);
            h[n] = fmaf(dA, h[n], xd * bvals[n]);
            yv = fmaf(h[n], cvals[n], yv);
        }
        float z = g_xz[(size_t)t * (2 * DINNER) + DINNER + d];
        g_y[(size_t)t * DINNER + d] = (yv + xv * Dd) * silu_f(z);
    }
}

// ---------------------------------------------------------------------------
// Launch
// ---------------------------------------------------------------------------
extern "C" void kernel_launch(void* const* d_in, const int* in_sizes, int n_in,
                              void* d_out, int out_size) {
    const float* x          = (const float*)d_in[0];
    const float* norm_w     = (const float*)d_in[1];
    const float* in_proj_w  = (const float*)d_in[2];
    const float* conv_w     = (const float*)d_in[3];
    const float* conv_b     = (const float*)d_in[4];
    const float* A_log      = (const float*)d_in[5];
    const float* projB_w    = (const float*)d_in[6];
    const float* projC_w    = (const float*)d_in[7];
    const float* projDelta_w= (const float*)d_in[8];
    const float* projDelta_b= (const float*)d_in[9];
    const float* Dw         = (const float*)d_in[10];
    const float* out_proj_w = (const float*)d_in[11];
    float* out = (float*)d_out;

    float *p_xn, *p_xz, *p_xc, *p_y;
    cudaGetSymbolAddress((void**)&p_xn, g_xn);
    cudaGetSymbolAddress((void**)&p_xz, g_xz);
    cudaGetSymbolAddress((void**)&p_xc, g_xc);
    cudaGetSymbolAddress((void**)&p_y,  g_y);
    float* p_wdbc;
    cudaGetSymbolAddress((void**)&p_wdbc, g_Wdbc);

    // 1. RMSNorm
    rmsnorm_kernel<<<NTOK, DMODEL>>>(x, norm_w, p_xn);

    // 2. concat delta/B/C weights (runs concurrently-safe before gemm<1>)
    concat_w_kernel<<<(NDBC * DINNER + 255) / 256, 256>>>(projDelta_w, projB_w, projC_w);

    // 3. in_proj: [8192,256] x [1024,256]^T -> g_xz [8192,1024]
    gemm_nt<0><<<dim3(2 * DINNER / GBN, NTOK / GBM), 256>>>(
        p_xn, in_proj_w, p_xz, NTOK, 2 * DINNER, DMODEL, nullptr, nullptr);

    // 4. causal conv + silu -> g_xc
    conv_silu_kernel<<<(NTOK * DINNER + 255) / 256, 256>>>(conv_w, conv_b);

    // 5. fused delta/B/C projections: [8192,512] x [640,512]^T
    gemm_nt<1><<<dim3(NDBC / GBN, NTOK / GBM), 256>>>(
        p_xc, p_wdbc, nullptr, NTOK, NDBC, DINNER, projDelta_b, nullptr);

    // 6-8. chunked selective scan
    scan_phaseA<<<dim3(DINNER / 128, NCH, BATCH), 128>>>(A_log);
    scan_phaseB<<<(BATCH * NSTATE * DINNER + 255) / 256, 256>>>();
    scan_phaseC<<<dim3(DINNER / 128, NCH, BATCH), 128>>>(A_log, Dw);

    // 9. out_proj + residual: [8192,512] x [256,512]^T + x
    gemm_nt<2><<<dim3(DMODEL / GBN, NTOK / GBM), 256>>>(
        p_y, out_proj_w, out, NTOK, DMODEL, DINNER, nullptr, x);
}

// round 2
// speedup vs baseline: 1.7308x; 1.7308x over previous
#include <cuda_runtime.h>
#include <cuda_bf16.h>
#include <math.h>
#include <stdint.h>

// ---------------------------------------------------------------------------
// Problem constants
// ---------------------------------------------------------------------------
#define BATCH   4
#define SEQL    2048
#define DMODEL  256
#define DINNER  512
#define NSTATE  16
#define DCONV   4
#define NTOK    (BATCH * SEQL)          // 8192
#define RMS_EPS 1.1920929e-07f

#define NCH     16                       // scan chunks
#define CT      (SEQL / NCH)             // 128 steps per chunk

#define NDBC    640                      // padded N for fused delta/B/C gemm (544 real)

// ---------------------------------------------------------------------------
// Scratch (static device globals; no allocation allowed)
// ---------------------------------------------------------------------------
__device__ float g_xn   [(size_t)NTOK * DMODEL];        // rmsnorm output
__device__ float g_xz   [(size_t)NTOK * 2 * DINNER];    // in_proj out: x_branch | z
__device__ float g_xc   [(size_t)NTOK * DINNER];        // conv + silu
__device__ float g_delta[(size_t)NTOK * DINNER];        // softplus(delta)
__device__ float g_BC   [(size_t)NTOK * 32];            // B_t (16) | C_t (16)
__device__ float g_Wdbc [(size_t)NDBC * DINNER];        // concat weights
__device__ float g_P    [(size_t)BATCH * NCH * NSTATE * DINNER];
__device__ float g_S    [(size_t)BATCH * NCH * NSTATE * DINNER];
__device__ float g_H    [(size_t)BATCH * NCH * NSTATE * DINNER];
__device__ float g_y    [(size_t)NTOK * DINNER];

// ---------------------------------------------------------------------------
// Helpers
// ---------------------------------------------------------------------------
__device__ __forceinline__ float silu_f(float v) {
    return v / (1.0f + __expf(-v));
}
__device__ __forceinline__ float softplus_f(float v) {
    return (v > 20.0f) ? v : log1pf(__expf(v));
}
__device__ __forceinline__ uint32_t f2tf32(float f) {
    uint32_t r;
    asm("cvt.rna.tf32.f32 %0, %1;" : "=r"(r) : "f"(f));
    return r;
}
__device__ __forceinline__ void mma_tf32(float (&d)[4], const uint32_t (&a)[4],
                                         const uint32_t (&b)[2]) {
    asm volatile(
        "mma.sync.aligned.m16n8k8.row.col.f32.tf32.tf32.f32 "
        "{%0,%1,%2,%3},{%4,%5,%6,%7},{%8,%9},{%0,%1,%2,%3};"
        : "+f"(d[0]), "+f"(d[1]), "+f"(d[2]), "+f"(d[3])
        : "r"(a[0]), "r"(a[1]), "r"(a[2]), "r"(a[3]), "r"(b[0]), "r"(b[1]));
}

// ---------------------------------------------------------------------------
// RMSNorm: one block per token
// ---------------------------------------------------------------------------
__global__ void rmsnorm_kernel(const float* __restrict__ x,
                               const float* __restrict__ w,
                               float* __restrict__ xn) {
    int t = blockIdx.x;
    int i = threadIdx.x;                 // 0..255
    float v = x[(size_t)t * DMODEL + i];
    float ss = v * v;
    #pragma unroll
    for (int o = 16; o; o >>= 1) ss += __shfl_xor_sync(0xFFFFFFFFu, ss, o);
    __shared__ float red[8];
    if ((i & 31) == 0) red[i >> 5] = ss;
    __syncthreads();
    float tot = 0.f;
    #pragma unroll
    for (int j = 0; j < 8; j++) tot += red[j];
    float scale = rsqrtf(tot * (1.0f / DMODEL) + RMS_EPS);
    xn[(size_t)t * DMODEL + i] = v * scale * w[i];
}

// ---------------------------------------------------------------------------
// Concatenate projDelta_w / projB_w / projC_w into one padded weight matrix
// ---------------------------------------------------------------------------
__global__ void concat_w_kernel(const float* __restrict__ wd,
                                const float* __restrict__ wb,
                                const float* __restrict__ wc) {
    int idx = blockIdx.x * blockDim.x + threadIdx.x;   // over NDBC*DINNER
    if (idx >= NDBC * DINNER) return;
    int r = idx / DINNER;
    int k = idx - r * DINNER;
    float v;
    if      (r < 512) v = wd[(size_t)r * DINNER + k];
    else if (r < 528) v = wb[(size_t)(r - 512) * DINNER + k];
    else if (r < 544) v = wc[(size_t)(r - 528) * DINNER + k];
    else              v = 0.0f;
    g_Wdbc[idx] = v;
}

// ---------------------------------------------------------------------------
// TF32 tensor-core GEMM: C[M,N] = A[M,K] * W[N,K]^T
// CTA tile 128x128x16, 8 warps, warp tile 64x32, mma.sync m16n8k8 tf32.
// 2-stage cp.async pipeline. Fused epilogues by EPI (same semantics as R1).
// ---------------------------------------------------------------------------
#define GBM 128
#define GBN 128
#define GBK 16
#define LDT 20   // padded smem row stride (floats): 16B-aligned, conflict-free

template<int EPI>
__global__ __launch_bounds__(256, 2)
void gemm_tc(const float* __restrict__ A, const float* __restrict__ W,
             float* __restrict__ C, int M, int N, int K,
             const float* __restrict__ bias,
             const float* __restrict__ resid) {
    __shared__ float As[2][GBM * LDT];
    __shared__ float Bs[2][GBN * LDT];

    const int tid  = threadIdx.x;
    const int m0   = blockIdx.y * GBM;
    const int n0   = blockIdx.x * GBN;
    const int lane = tid & 31;
    const int wid  = tid >> 5;
    const int wm   = wid & 1;          // warp row (2)
    const int wn   = wid >> 1;         // warp col (4)
    const int g    = lane >> 2;        // 0..7
    const int t4   = lane & 3;         // 0..3

    float acc[4][4][4];
    #pragma unroll
    for (int mf = 0; mf < 4; mf++)
        #pragma unroll
        for (int nf = 0; nf < 4; nf++)
            #pragma unroll
            for (int r = 0; r < 4; r++) acc[mf][nf][r] = 0.0f;

    // cp.async loader: 1024 16B-chunks (512 for A tile, 512 for B tile)
    auto issue = [&](int stage, int k0) {
        #pragma unroll
        for (int i = 0; i < 4; i++) {
            int c    = tid + i * 256;
            int row  = (c >> 2) & 127;
            int part = (c & 3) * 4;
            const float* src;
            float* dstf;
            if (c < 512) {
                src  = A + (size_t)(m0 + row) * K + k0 + part;
                dstf = &As[stage][row * LDT + part];
            } else {
                src  = W + (size_t)(n0 + row) * K + k0 + part;
                dstf = &Bs[stage][row * LDT + part];
            }
            uint32_t dsts = (uint32_t)__cvta_generic_to_shared(dstf);
            asm volatile("cp.async.cg.shared.global [%0], [%1], 16;"
                         :: "r"(dsts), "l"(src));
        }
        asm volatile("cp.async.commit_group;");
    };

    const int niter = K / GBK;
    issue(0, 0);

    for (int it = 0; it < niter; it++) {
        if (it + 1 < niter) {
            issue((it + 1) & 1, (it + 1) * GBK);
            asm volatile("cp.async.wait_group 1;");
        } else {
            asm volatile("cp.async.wait_group 0;");
        }
        __syncthreads();

        const float* as = As[it & 1];
        const float* bs = Bs[it & 1];

        #pragma unroll
        for (int kc = 0; kc < 2; kc++) {
            const int kk = kc * 8 + t4;
            uint32_t af[4][4], bf[4][2];
            #pragma unroll
            for (int mf = 0; mf < 4; mf++) {
                int bm = wm * 64 + mf * 16 + g;
                af[mf][0] = f2tf32(as[bm * LDT + kk]);
                af[mf][1] = f2tf32(as[(bm + 8) * LDT + kk]);
                af[mf][2] = f2tf32(as[bm * LDT + kk + 4]);
                af[mf][3] = f2tf32(as[(bm + 8) * LDT + kk + 4]);
            }
            #pragma unroll
            for (int nf = 0; nf < 4; nf++) {
                int bn = wn * 32 + nf * 8 + g;
                bf[nf][0] = f2tf32(bs[bn * LDT + kk]);
                bf[nf][1] = f2tf32(bs[bn * LDT + kk + 4]);
            }
            #pragma unroll
            for (int mf = 0; mf < 4; mf++)
                #pragma unroll
                for (int nf = 0; nf < 4; nf++)
                    mma_tf32(acc[mf][nf], af[mf], bf[nf]);
        }
        __syncthreads();
    }

    // Epilogue
    #pragma unroll
    for (int mf = 0; mf < 4; mf++) {
        #pragma unroll
        for (int nf = 0; nf < 4; nf++) {
            #pragma unroll
            for (int r = 0; r < 4; r++) {
                int t = m0 + wm * 64 + mf * 16 + g + ((r >> 1) ? 8 : 0);
                int n = n0 + wn * 32 + nf * 8 + t4 * 2 + (r & 1);
                float v = acc[mf][nf][r];
                if (EPI == 0) {
                    C[(size_t)t * N + n] = v;
                } else if (EPI == 1) {
                    if (n < 512) {
                        g_delta[(size_t)t * DINNER + n] = softplus_f(v + bias[n]);
                    } else if (n < 544) {
                        g_BC[(size_t)t * 32 + (n - 512)] = v;
                    }
                } else { // EPI == 2
                    C[(size_t)t * N + n] = v + resid[(size_t)t * N + n];
                }
            }
        }
    }
}

// ---------------------------------------------------------------------------
// Causal depthwise conv (width 4) + bias + SiLU. Each thread does 4 timesteps.
// ---------------------------------------------------------------------------
__global__ void conv_silu_kernel(const float* __restrict__ cw,
                                 const float* __restrict__ cb) {
    int q = blockIdx.x * blockDim.x + threadIdx.x;   // over (NTOK/4)*512
    if (q >= (NTOK / 4) * DINNER) return;
    int d  = q & 511;
    int t0 = (q >> 9) * 4;
    int l0 = t0 & (SEQL - 1);
    float w0 = cw[d * 4 + 0], w1 = cw[d * 4 + 1];
    float w2 = cw[d * 4 + 2], w3 = cw[d * 4 + 3];
    float b = cb[d];
    float xv[7];
    #pragma unroll
    for (int i = 0; i < 7; i++) {
        int li = l0 - 3 + i;
        xv[i] = (li >= 0) ? g_xz[(size_t)(t0 - 3 + i) * (2 * DINNER) + d] : 0.0f;
    }
    #pragma unroll
    for (int j = 0; j < 4; j++) {
        float a = fmaf(w3, xv[j + 3], fmaf(w2, xv[j + 2],
                  fmaf(w1, xv[j + 1], fmaf(w0, xv[j], b))));
        g_xc[(size_t)(t0 + j) * DINNER + d] = silu_f(a);
    }
}

// ---------------------------------------------------------------------------
// Scan pass A: per-chunk decay product P and zero-init end state S.
// ---------------------------------------------------------------------------
__global__ void scan_phaseA(const float* __restrict__ A_log) {
    int d = blockIdx.x * 128 + threadIdx.x;
    int c = blockIdx.y;
    int b = blockIdx.z;

    float A2[NSTATE], h[NSTATE], p[NSTATE];
    #pragma unroll
    for (int n = 0; n < NSTATE; n++) {
        A2[n] = -__expf(A_log[d * NSTATE + n]) * 1.4426950408889634f;
        h[n] = 0.0f;
        p[n] = 1.0f;
    }
    int tbase = b * SEQL + c * CT;
    for (int s = 0; s < CT; s++) {
        int t = tbase + s;
        float dl = g_delta[(size_t)t * DINNER + d];
        float xv = g_xc  [(size_t)t * DINNER + d];
        float xd = xv * dl;
        const float4* bc = (const float4*)(g_BC + (size_t)t * 32);
        float4 b0 = bc[0], b1 = bc[1], b2 = bc[2], b3 = bc[3];
        float bvals[NSTATE] = {b0.x,b0.y,b0.z,b0.w, b1.x,b1.y,b1.z,b1.w,
                               b2.x,b2.y,b2.z,b2.w, b3.x,b3.y,b3.z,b3.w};
        #pragma unroll
        for (int n = 0; n < NSTATE; n++) {
            float dA = exp2f(dl * A2[n]);
            h[n] = fmaf(dA, h[n], xd * bvals[n]);
            p[n] *= dA;
        }
    }
    size_t base = (((size_t)b * NCH + c) * NSTATE) * DINNER + d;
    #pragma unroll
    for (int n = 0; n < NSTATE; n++) {
        g_P[base + (size_t)n * DINNER] = p[n];
        g_S[base + (size_t)n * DINNER] = h[n];
    }
}

// ---------------------------------------------------------------------------
// Scan pass B: sequential carry across chunks (tiny).
// ---------------------------------------------------------------------------
__global__ void scan_phaseB() {
    int idx = blockIdx.x * blockDim.x + threadIdx.x;
    if (idx >= BATCH * NSTATE * DINNER) return;
    int d = idx & 511;
    int n = (idx >> 9) & 15;
    int b = idx >> 13;
    float h = 0.0f;
    for (int c = 0; c < NCH; c++) {
        size_t o = (((size_t)b * NCH + c) * NSTATE + n) * DINNER + d;
        g_H[o] = h;
        h = fmaf(g_P[o], h, g_S[o]);
    }
}

// ---------------------------------------------------------------------------
// Scan pass C: rerun chunk with true initial state; fused +x*D, *silu(z).
// ---------------------------------------------------------------------------
__global__ void scan_phaseC(const float* __restrict__ A_log,
                            const float* __restrict__ Dw) {
    int d = blockIdx.x * 128 + threadIdx.x;
    int c = blockIdx.y;
    int b = blockIdx.z;

    float A2[NSTATE], h[NSTATE];
    size_t hbase = (((size_t)b * NCH + c) * NSTATE) * DINNER + d;
    #pragma unroll
    for (int n = 0; n < NSTATE; n++) {
        A2[n] = -__expf(A_log[d * NSTATE + n]) * 1.4426950408889634f;
        h[n] = g_H[hbase + (size_t)n * DINNER];
    }
    float Dd = Dw[d];
    int tbase = b * SEQL + c * CT;
    for (int s = 0; s < CT; s++) {
        int t = tbase + s;
        float dl = g_delta[(size_t)t * DINNER + d];
        float xv = g_xc  [(size_t)t * DINNER + d];
        float xd = xv * dl;
        const float4* bc = (const float4*)(g_BC + (size_t)t * 32);
        float4 b0 = bc[0], b1 = bc[1], b2 = bc[2], b3 = bc[3];
        float4 c0 = bc[4], c1 = bc[5], c2 = bc[6], c3 = bc[7];
        float bvals[NSTATE] = {b0.x,b0.y,b0.z,b0.w, b1.x,b1.y,b1.z,b1.w,
                               b2.x,b2.y,b2.z,b2.w, b3.x,b3.y,b3.z,b3.w};
        float cvals[NSTATE] = {c0.x,c0.y,c0.z,c0.w, c1.x,c1.y,c1.z,c1.w,
                               c2.x,c2.y,c2.z,c2.w, c3.x,c3.y,c3.z,c3.w};
        float yv = 0.0f;
        #pragma unroll
        for (int n = 0; n < NSTATE; n++) {
            float dA = exp2f(dl * A2[n]);
            h[n] = fmaf(dA, h[n], xd * bvals[n]);
            yv = fmaf(h[n], cvals[n], yv);
        }
        float z = g_xz[(size_t)t * (2 * DINNER) + DINNER + d];
        g_y[(size_t)t * DINNER + d] = (yv + xv * Dd) * silu_f(z);
    }
}

// ---------------------------------------------------------------------------
// Launch
// ---------------------------------------------------------------------------
extern "C" void kernel_launch(void* const* d_in, const int* in_sizes, int n_in,
                              void* d_out, int out_size) {
    const float* x          = (const float*)d_in[0];
    const float* norm_w     = (const float*)d_in[1];
    const float* in_proj_w  = (const float*)d_in[2];
    const float* conv_w     = (const float*)d_in[3];
    const float* conv_b     = (const float*)d_in[4];
    const float* A_log      = (const float*)d_in[5];
    const float* projB_w    = (const float*)d_in[6];
    const float* projC_w    = (const float*)d_in[7];
    const float* projDelta_w= (const float*)d_in[8];
    const float* projDelta_b= (const float*)d_in[9];
    const float* Dw         = (const float*)d_in[10];
    const float* out_proj_w = (const float*)d_in[11];
    float* out = (float*)d_out;

    float *p_xn, *p_xz, *p_xc, *p_y, *p_wdbc;
    cudaGetSymbolAddress((void**)&p_xn, g_xn);
    cudaGetSymbolAddress((void**)&p_xz, g_xz);
    cudaGetSymbolAddress((void**)&p_xc, g_xc);
    cudaGetSymbolAddress((void**)&p_y,  g_y);
    cudaGetSymbolAddress((void**)&p_wdbc, g_Wdbc);

    // 1. RMSNorm
    rmsnorm_kernel<<<NTOK, DMODEL>>>(x, norm_w, p_xn);

    // 2. concat delta/B/C weights
    concat_w_kernel<<<(NDBC * DINNER + 255) / 256, 256>>>(projDelta_w, projB_w, projC_w);

    // 3. in_proj: [8192,256] x [1024,256]^T -> g_xz
    gemm_tc<0><<<dim3(2 * DINNER / GBN, NTOK / GBM), 256>>>(
        p_xn, in_proj_w, p_xz, NTOK, 2 * DINNER, DMODEL, nullptr, nullptr);

    // 4. causal conv + silu -> g_xc
    conv_silu_kernel<<<((NTOK / 4) * DINNER + 255) / 256, 256>>>(conv_w, conv_b);

    // 5. fused delta/B/C projections: [8192,512] x [640,512]^T
    gemm_tc<1><<<dim3(NDBC / GBN, NTOK / GBM), 256>>>(
        p_xc, p_wdbc, nullptr, NTOK, NDBC, DINNER, projDelta_b, nullptr);

    // 6-8. chunked selective scan
    scan_phaseA<<<dim3(DINNER / 128, NCH, BATCH), 128>>>(A_log);
    scan_phaseB<<<(BATCH * NSTATE * DINNER + 255) / 256, 256>>>();
    scan_phaseC<<<dim3(DINNER / 128, NCH, BATCH), 128>>>(A_log, Dw);

    // 9. out_proj + residual: [8192,512] x [256,512]^T + x
    gemm_tc<2><<<dim3(DMODEL / GBN, NTOK / GBM), 256>>>(
        p_y, out_proj_w, out, NTOK, DMODEL, DINNER, nullptr, x);
}

// round 3
// speedup vs baseline: 2.2760x; 1.3150x over previous
#include <cuda_runtime.h>
#include <cuda_bf16.h>
#include <math.h>
#include <stdint.h>

// ---------------------------------------------------------------------------
// Problem constants
// ---------------------------------------------------------------------------
#define BATCH   4
#define SEQL    2048
#define DMODEL  256
#define DINNER  512
#define NSTATE  16
#define DCONV   4
#define NTOK    (BATCH * SEQL)          // 8192
#define RMS_EPS 1.1920929e-07f

#define NCH     32                       // scan chunks
#define CT      (SEQL / NCH)             // 64 steps per chunk

#define NDBC    640                      // padded N for fused delta/B/C gemm

// ---------------------------------------------------------------------------
// Scratch (static device globals; no allocation allowed)
// ---------------------------------------------------------------------------
__device__ float g_xz   [(size_t)NTOK * 2 * DINNER];    // in_proj out: x_branch | z
__device__ float g_xc   [(size_t)NTOK * DINNER];        // conv + silu
__device__ float g_delta[(size_t)NTOK * DINNER];        // softplus(delta)
__device__ float g_BC   [(size_t)NTOK * 32];            // B_t (16) | C_t (16)
__device__ float g_Wdbc [(size_t)NDBC * DINNER];        // concat weights
__device__ float g_Win  [(size_t)(2 * DINNER) * DMODEL];// in_proj_w * norm_w
__device__ float g_P    [(size_t)BATCH * NCH * NSTATE * DINNER];
__device__ float g_S    [(size_t)BATCH * NCH * NSTATE * DINNER];
__device__ float g_H    [(size_t)BATCH * NCH * NSTATE * DINNER];
__device__ float g_y    [(size_t)NTOK * DINNER];

// ---------------------------------------------------------------------------
// Helpers
// ---------------------------------------------------------------------------
__device__ __forceinline__ float silu_f(float v) {
    return v / (1.0f + __expf(-v));
}
__device__ __forceinline__ float softplus_f(float v) {
    return (v > 20.0f) ? v : log1pf(__expf(v));
}
__device__ __forceinline__ void mma_tf32(float (&d)[4], const uint32_t (&a)[4],
                                         const uint32_t (&b)[2]) {
    asm volatile(
        "mma.sync.aligned.m16n8k8.row.col.f32.tf32.tf32.f32 "
        "{%0,%1,%2,%3},{%4,%5,%6,%7},{%8,%9},{%0,%1,%2,%3};"
        : "+f"(d[0]), "+f"(d[1]), "+f"(d[2]), "+f"(d[3])
        : "r"(a[0]), "r"(a[1]), "r"(a[2]), "r"(a[3]), "r"(b[0]), "r"(b[1]));
}

// ---------------------------------------------------------------------------
// Weight prep: concat projDelta/projB/projC (padded), and in_proj_w * norm_w
// ---------------------------------------------------------------------------
#define NDBC_ELEMS (NDBC * DINNER)                 // 327680
#define WIN_ELEMS  (2 * DINNER * DMODEL)           // 262144
__global__ void prep_w_kernel(const float* __restrict__ wd,
                              const float* __restrict__ wb,
                              const float* __restrict__ wc,
                              const float* __restrict__ win,
                              const float* __restrict__ normw) {
    int idx = blockIdx.x * blockDim.x + threadIdx.x;
    if (idx < NDBC_ELEMS) {
        int r = idx / DINNER;
        int k = idx - r * DINNER;
        float v;
        if      (r < 512) v = wd[(size_t)r * DINNER + k];
        else if (r < 528) v = wb[(size_t)(r - 512) * DINNER + k];
        else if (r < 544) v = wc[(size_t)(r - 528) * DINNER + k];
        else              v = 0.0f;
        g_Wdbc[idx] = v;
    }
    int j = idx - NDBC_ELEMS;
    if (j >= 0 && j < WIN_ELEMS) {
        int k = j & (DMODEL - 1);
        g_Win[j] = win[j] * normw[k];
    }
}

// ---------------------------------------------------------------------------
// TF32 tensor-core GEMM: C[M,N] = A[M,K] * W[N,K]^T
// CTA tile 128x128x16, 8 warps, warp tile 64x32, mma.sync m16n8k8 tf32.
// Raw f32 bits fed to mma (HW truncation to tf32 -- no cvt).
// FRMS: fuse RMSNorm row-scale into the A operand (K must be 256).
//  EPI 0: plain store                                   -> in_proj
//  EPI 1: softplus(+bias) -> g_delta ; cols 512..543 -> g_BC
//  EPI 2: + resid                                       -> out_proj
// ---------------------------------------------------------------------------
#define GBM 128
#define GBN 128
#define GBK 16
#define LDT 20   // padded smem row stride (floats)

template<int EPI, bool FRMS>
__global__ __launch_bounds__(256, 2)
void gemm_tc(const float* __restrict__ A, const float* __restrict__ W,
             float* __restrict__ C, int M, int N, int K,
             const float* __restrict__ bias,
             const float* __restrict__ resid) {
    __shared__ float As[2][GBM * LDT];
    __shared__ float Bs[2][GBN * LDT];
    __shared__ float sScale[GBM];

    const int tid  = threadIdx.x;
    const int m0   = blockIdx.y * GBM;
    const int n0   = blockIdx.x * GBN;
    const int lane = tid & 31;
    const int wid  = tid >> 5;
    const int wm   = wid & 1;          // warp row (2)
    const int wn   = wid >> 1;         // warp col (4)
    const int g    = lane >> 2;        // 0..7
    const int t4   = lane & 3;         // 0..3

    // Fused RMSNorm: per-row scale for this CTA's 128 rows
    if (FRMS) {
        int r  = tid >> 1;
        int hh = tid & 1;
        const float4* xp = (const float4*)(A + (size_t)(m0 + r) * K + hh * (K / 2));
        float s = 0.0f;
        #pragma unroll
        for (int i = 0; i < 32; i++) {
            float4 v = xp[i];
            s = fmaf(v.x, v.x, s); s = fmaf(v.y, v.y, s);
            s = fmaf(v.z, v.z, s); s = fmaf(v.w, v.w, s);
        }
        float o = __shfl_xor_sync(0xFFFFFFFFu, s, 1);
        if (hh == 0)
            sScale[r] = rsqrtf((s + o) * (1.0f / DMODEL) + RMS_EPS);
    }

    float acc[4][4][4];
    #pragma unroll
    for (int mf = 0; mf < 4; mf++)
        #pragma unroll
        for (int nf = 0; nf < 4; nf++)
            #pragma unroll
            for (int r = 0; r < 4; r++) acc[mf][nf][r] = 0.0f;

    auto issue = [&](int stage, int k0) {
        #pragma unroll
        for (int i = 0; i < 4; i++) {
            int c    = tid + i * 256;
            int row  = (c >> 2) & 127;
            int part = (c & 3) * 4;
            const float* src;
            float* dstf;
            if (c < 512) {
                src  = A + (size_t)(m0 + row) * K + k0 + part;
                dstf = &As[stage][row * LDT + part];
            } else {
                src  = W + (size_t)(n0 + row) * K + k0 + part;
                dstf = &Bs[stage][row * LDT + part];
            }
            uint32_t dsts = (uint32_t)__cvta_generic_to_shared(dstf);
            asm volatile("cp.async.cg.shared.global [%0], [%1], 16;"
                         :: "r"(dsts), "l"(src));
        }
        asm volatile("cp.async.commit_group;");
    };

    const int niter = K / GBK;
    issue(0, 0);

    for (int it = 0; it < niter; it++) {
        if (it + 1 < niter) {
            issue((it + 1) & 1, (it + 1) * GBK);
            asm volatile("cp.async.wait_group 1;");
        } else {
            asm volatile("cp.async.wait_group 0;");
        }
        __syncthreads();

        const float* as = As[it & 1];
        const float* bs = Bs[it & 1];

        #pragma unroll
        for (int kc = 0; kc < 2; kc++) {
            const int kk = kc * 8 + t4;
            uint32_t af[4][4], bf[4][2];
            #pragma unroll
            for (int mf = 0; mf < 4; mf++) {
                int bm = wm * 64 + mf * 16 + g;
                if (FRMS) {
                    float s0 = sScale[bm], s1 = sScale[bm + 8];
                    af[mf][0] = __float_as_uint(as[bm * LDT + kk] * s0);
                    af[mf][1] = __float_as_uint(as[(bm + 8) * LDT + kk] * s1);
                    af[mf][2] = __float_as_uint(as[bm * LDT + kk + 4] * s0);
                    af[mf][3] = __float_as_uint(as[(bm + 8) * LDT + kk + 4] * s1);
                } else {
                    af[mf][0] = __float_as_uint(as[bm * LDT + kk]);
                    af[mf][1] = __float_as_uint(as[(bm + 8) * LDT + kk]);
                    af[mf][2] = __float_as_uint(as[bm * LDT + kk + 4]);
                    af[mf][3] = __float_as_uint(as[(bm + 8) * LDT + kk + 4]);
                }
            }
            #pragma unroll
            for (int nf = 0; nf < 4; nf++) {
                int bn = wn * 32 + nf * 8 + g;
                bf[nf][0] = __float_as_uint(bs[bn * LDT + kk]);
                bf[nf][1] = __float_as_uint(bs[bn * LDT + kk + 4]);
            }
            #pragma unroll
            for (int mf = 0; mf < 4; mf++)
                #pragma unroll
                for (int nf = 0; nf < 4; nf++)
                    mma_tf32(acc[mf][nf], af[mf], bf[nf]);
        }
        __syncthreads();
    }

    // Epilogue
    #pragma unroll
    for (int mf = 0; mf < 4; mf++) {
        #pragma unroll
        for (int nf = 0; nf < 4; nf++) {
            #pragma unroll
            for (int r = 0; r < 4; r++) {
                int t = m0 + wm * 64 + mf * 16 + g + ((r >> 1) ? 8 : 0);
                int n = n0 + wn * 32 + nf * 8 + t4 * 2 + (r & 1);
                float v = acc[mf][nf][r];
                if (EPI == 0) {
                    C[(size_t)t * N + n] = v;
                } else if (EPI == 1) {
                    if (n < 512) {
                        g_delta[(size_t)t * DINNER + n] = softplus_f(v + bias[n]);
                    } else if (n < 544) {
                        g_BC[(size_t)t * 32 + (n - 512)] = v;
                    }
                } else { // EPI == 2
                    C[(size_t)t * N + n] = v + resid[(size_t)t * N + n];
                }
            }
        }
    }
}

// ---------------------------------------------------------------------------
// Causal depthwise conv (width 4) + bias + SiLU. Each thread does 8 timesteps.
// ---------------------------------------------------------------------------
__global__ void conv_silu_kernel(const float* __restrict__ cw,
                                 const float* __restrict__ cb) {
    int q = blockIdx.x * blockDim.x + threadIdx.x;   // over (NTOK/8)*512
    if (q >= (NTOK / 8) * DINNER) return;
    int d  = q & 511;
    int t0 = (q >> 9) * 8;
    int l0 = t0 & (SEQL - 1);
    float w0 = cw[d * 4 + 0], w1 = cw[d * 4 + 1];
    float w2 = cw[d * 4 + 2], w3 = cw[d * 4 + 3];
    float b = cb[d];
    float xv[11];
    #pragma unroll
    for (int i = 0; i < 11; i++) {
        int li = l0 - 3 + i;
        xv[i] = (li >= 0) ? g_xz[(size_t)(t0 - 3 + i) * (2 * DINNER) + d] : 0.0f;
    }
    #pragma unroll
    for (int j = 0; j < 8; j++) {
        float a = fmaf(w3, xv[j + 3], fmaf(w2, xv[j + 2],
                  fmaf(w1, xv[j + 1], fmaf(w0, xv[j], b))));
        g_xc[(size_t)(t0 + j) * DINNER + d] = silu_f(a);
    }
}

// ---------------------------------------------------------------------------
// Scan pass A: per-chunk end-state S; decay product P via exp2(A2 * sum delta).
// grid (DINNER/128, NCH, BATCH), 128 threads; thread owns (b, chunk, d).
// ---------------------------------------------------------------------------
__global__ void scan_phaseA(const float* __restrict__ A_log) {
    int d = blockIdx.x * 128 + threadIdx.x;
    int c = blockIdx.y;
    int b = blockIdx.z;

    float A2[NSTATE], h[NSTATE];
    #pragma unroll
    for (int n = 0; n < NSTATE; n++) {
        A2[n] = -__expf(A_log[d * NSTATE + n]) * 1.4426950408889634f;
        h[n] = 0.0f;
    }
    float sdl = 0.0f;
    int tbase = b * SEQL + c * CT;
    #pragma unroll 2
    for (int s = 0; s < CT; s++) {
        int t = tbase + s;
        float dl = g_delta[(size_t)t * DINNER + d];
        float xv = g_xc  [(size_t)t * DINNER + d];
        float xd = xv * dl;
        sdl += dl;
        const float4* bc = (const float4*)(g_BC + (size_t)t * 32);
        float4 b0 = bc[0], b1 = bc[1], b2 = bc[2], b3 = bc[3];
        float bvals[NSTATE] = {b0.x,b0.y,b0.z,b0.w, b1.x,b1.y,b1.z,b1.w,
                               b2.x,b2.y,b2.z,b2.w, b3.x,b3.y,b3.z,b3.w};
        #pragma unroll
        for (int n = 0; n < NSTATE; n++) {
            float dA = exp2f(dl * A2[n]);
            h[n] = fmaf(dA, h[n], xd * bvals[n]);
        }
    }
    size_t base = (((size_t)b * NCH + c) * NSTATE) * DINNER + d;
    #pragma unroll
    for (int n = 0; n < NSTATE; n++) {
        g_P[base + (size_t)n * DINNER] = exp2f(A2[n] * sdl);
        g_S[base + (size_t)n * DINNER] = h[n];
    }
}

// ---------------------------------------------------------------------------
// Scan pass B: sequential carry across chunks (tiny).
// ---------------------------------------------------------------------------
__global__ void scan_phaseB() {
    int idx = blockIdx.x * blockDim.x + threadIdx.x;
    if (idx >= BATCH * NSTATE * DINNER) return;
    int d = idx & 511;
    int n = (idx >> 9) & 15;
    int b = idx >> 13;
    float h = 0.0f;
    for (int c = 0; c < NCH; c++) {
        size_t o = (((size_t)b * NCH + c) * NSTATE + n) * DINNER + d;
        g_H[o] = h;
        h = fmaf(g_P[o], h, g_S[o]);
    }
}

// ---------------------------------------------------------------------------
// Scan pass C: rerun chunk with true initial state; fused +x*D, *silu(z).
// ---------------------------------------------------------------------------
__global__ void scan_phaseC(const float* __restrict__ A_log,
                            const float* __restrict__ Dw) {
    int d = blockIdx.x * 128 + threadIdx.x;
    int c = blockIdx.y;
    int b = blockIdx.z;

    float A2[NSTATE], h[NSTATE];
    size_t hbase = (((size_t)b * NCH + c) * NSTATE) * DINNER + d;
    #pragma unroll
    for (int n = 0; n < NSTATE; n++) {
        A2[n] = -__expf(A_log[d * NSTATE + n]) * 1.4426950408889634f;
        h[n] = g_H[hbase + (size_t)n * DINNER];
    }
    float Dd = Dw[d];
    int tbase = b * SEQL + c * CT;
    #pragma unroll 2
    for (int s = 0; s < CT; s++) {
        int t = tbase + s;
        float dl = g_delta[(size_t)t * DINNER + d];
        float xv = g_xc  [(size_t)t * DINNER + d];
        float xd = xv * dl;
        const float4* bc = (const float4*)(g_BC + (size_t)t * 32);
        float4 b0 = bc[0], b1 = bc[1], b2 = bc[2], b3 = bc[3];
        float4 c0 = bc[4], c1 = bc[5], c2 = bc[6], c3 = bc[7];
        float bvals[NSTATE] = {b0.x,b0.y,b0.z,b0.w, b1.x,b1.y,b1.z,b1.w,
                               b2.x,b2.y,b2.z,b2.w, b3.x,b3.y,b3.z,b3.w};
        float cvals[NSTATE] = {c0.x,c0.y,c0.z,c0.w, c1.x,c1.y,c1.z,c1.w,
                               c2.x,c2.y,c2.z,c2.w, c3.x,c3.y,c3.z,c3.w};
        float yv = 0.0f;
        #pragma unroll
        for (int n = 0; n < NSTATE; n++) {
            float dA = exp2f(dl * A2[n]);
            h[n] = fmaf(dA, h[n], xd * bvals[n]);
            yv = fmaf(h[n], cvals[n], yv);
        }
        float z = g_xz[(size_t)t * (2 * DINNER) + DINNER + d];
        g_y[(size_t)t * DINNER + d] = (yv + xv * Dd) * silu_f(z);
    }
}

// ---------------------------------------------------------------------------
// Launch
// ---------------------------------------------------------------------------
extern "C" void kernel_launch(void* const* d_in, const int* in_sizes, int n_in,
                              void* d_out, int out_size) {
    const float* x          = (const float*)d_in[0];
    const float* norm_w     = (const float*)d_in[1];
    const float* in_proj_w  = (const float*)d_in[2];
    const float* conv_w     = (const float*)d_in[3];
    const float* conv_b     = (const float*)d_in[4];
    const float* A_log      = (const float*)d_in[5];
    const float* projB_w    = (const float*)d_in[6];
    const float* projC_w    = (const float*)d_in[7];
    const float* projDelta_w= (const float*)d_in[8];
    const float* projDelta_b= (const float*)d_in[9];
    const float* Dw         = (const float*)d_in[10];
    const float* out_proj_w = (const float*)d_in[11];
    float* out = (float*)d_out;

    float *p_xz, *p_xc, *p_y, *p_wdbc, *p_win;
    cudaGetSymbolAddress((void**)&p_xz, g_xz);
    cudaGetSymbolAddress((void**)&p_xc, g_xc);
    cudaGetSymbolAddress((void**)&p_y,  g_y);
    cudaGetSymbolAddress((void**)&p_wdbc, g_Wdbc);
    cudaGetSymbolAddress((void**)&p_win,  g_Win);

    // 1. weight prep (concat dbc, fold norm_w into in_proj)
    prep_w_kernel<<<(NDBC_ELEMS + WIN_ELEMS + 255) / 256, 256>>>(
        projDelta_w, projB_w, projC_w, in_proj_w, norm_w);

    // 2. in_proj with fused RMSNorm: [8192,256] x [1024,256]^T -> g_xz
    gemm_tc<0, true><<<dim3(2 * DINNER / GBN, NTOK / GBM), 256>>>(
        x, p_win, p_xz, NTOK, 2 * DINNER, DMODEL, nullptr, nullptr);

    // 3. causal conv + silu -> g_xc
    conv_silu_kernel<<<((NTOK / 8) * DINNER + 255) / 256, 256>>>(conv_w, conv_b);

    // 4. fused delta/B/C projections: [8192,512] x [640,512]^T
    gemm_tc<1, false><<<dim3(NDBC / GBN, NTOK / GBM), 256>>>(
        p_xc, p_wdbc, nullptr, NTOK, NDBC, DINNER, projDelta_b, nullptr);

    // 5-7. chunked selective scan
    scan_phaseA<<<dim3(DINNER / 128, NCH, BATCH), 128>>>(A_log);
    scan_phaseB<<<(BATCH * NSTATE * DINNER + 255) / 256, 256>>>();
    scan_phaseC<<<dim3(DINNER / 128, NCH, BATCH), 128>>>(A_log, Dw);

    // 8. out_proj + residual: [8192,512] x [256,512]^T + x
    gemm_tc<2, false><<<dim3(DMODEL / GBN, NTOK / GBM), 256>>>(
        p_y, out_proj_w, out, NTOK, DMODEL, DINNER, nullptr, x);
}

// round 5
// speedup vs baseline: 3.1965x; 1.4044x over previous
#include <cuda_runtime.h>
#include <cuda_bf16.h>
#include <math.h>
#include <stdint.h>

// ---------------------------------------------------------------------------
// Problem constants
// ---------------------------------------------------------------------------
#define BATCH   4
#define SEQL    2048
#define DMODEL  256
#define DINNER  512
#define NSTATE  16
#define NTOK    (BATCH * SEQL)          // 8192
#define RMS_EPS 1.1920929e-07f

#define NCH     64                       // scan chunks
#define CT      (SEQL / NCH)             // 32 steps per chunk

#define NDBC    640                      // padded N for fused delta/B/C gemm

// ---------------------------------------------------------------------------
// Scratch (static device globals; no allocation allowed)
// ---------------------------------------------------------------------------
__device__ __nv_bfloat16 g_xnb  [(size_t)NTOK * DMODEL];      // rmsnorm (bf16)
__device__ float         g_xz   [(size_t)NTOK * 2 * DINNER];  // x_branch | z
__device__ float         g_xc   [(size_t)NTOK * DINNER];      // conv+silu fp32
__device__ __nv_bfloat16 g_xcb  [(size_t)NTOK * DINNER];      // conv+silu bf16
__device__ float         g_delta[(size_t)NTOK * DINNER];
__device__ float         g_BC   [(size_t)NTOK * 32];          // B(16) | C(16)
__device__ __nv_bfloat16 g_Winb [(size_t)(2 * DINNER) * DMODEL];
__device__ __nv_bfloat16 g_Wdbcb[(size_t)NDBC * DINNER];
__device__ __nv_bfloat16 g_Woutb[(size_t)DMODEL * DINNER];
__device__ __nv_bfloat16 g_yb   [(size_t)NTOK * DINNER];
__device__ float g_P[(size_t)BATCH * NCH * NSTATE * DINNER];
__device__ float g_S[(size_t)BATCH * NCH * NSTATE * DINNER];
__device__ float g_H[(size_t)BATCH * NCH * NSTATE * DINNER];

// ---------------------------------------------------------------------------
// Helpers
// ---------------------------------------------------------------------------
__device__ __forceinline__ float silu_f(float v) { return v / (1.0f + __expf(-v)); }
__device__ __forceinline__ float softplus_f(float v) {
    return (v > 20.0f) ? v : log1pf(__expf(v));
}
__device__ __forceinline__ void mma_bf16(float (&d)[4], const uint32_t (&a)[4],
                                         const uint32_t (&b)[2]) {
    asm volatile(
        "mma.sync.aligned.m16n8k16.row.col.f32.bf16.bf16.f32 "
        "{%0,%1,%2,%3},{%4,%5,%6,%7},{%8,%9},{%0,%1,%2,%3};"
        : "+f"(d[0]), "+f"(d[1]), "+f"(d[2]), "+f"(d[3])
        : "r"(a[0]), "r"(a[1]), "r"(a[2]), "r"(a[3]), "r"(b[0]), "r"(b[1]));
}
#define CP_ASYNC16(dst, src) \
    asm volatile("cp.async.cg.shared.global [%0], [%1], 16;" :: "r"(dst), "l"(src))
#define CP_COMMIT() asm volatile("cp.async.commit_group;")

// ---------------------------------------------------------------------------
// Weight prep: bf16 conversions (+ norm_w folded into in_proj weights)
// ---------------------------------------------------------------------------
#define WIN_E  (2 * DINNER * DMODEL)    // 262144
#define WDBC_E (NDBC * DINNER)          // 327680
#define WOUT_E (DMODEL * DINNER)        // 131072
__global__ void prep_w_kernel(const float* __restrict__ win,
                              const float* __restrict__ normw,
                              const float* __restrict__ wd,
                              const float* __restrict__ wb,
                              const float* __restrict__ wc,
                              const float* __restrict__ wout) {
    int idx = blockIdx.x * blockDim.x + threadIdx.x;
    if (idx < WIN_E) {
        int k = idx & (DMODEL - 1);
        g_Winb[idx] = __float2bfloat16(win[idx] * normw[k]);
    }
    int j = idx - WIN_E;
    if (j >= 0 && j < WDBC_E) {
        int r = j / DINNER;
        int k = j - r * DINNER;
        float v;
        if      (r < 512) v = wd[(size_t)r * DINNER + k];
        else if (r < 528) v = wb[(size_t)(r - 512) * DINNER + k];
        else if (r < 544) v = wc[(size_t)(r - 528) * DINNER + k];
        else              v = 0.0f;
        g_Wdbcb[j] = __float2bfloat16(v);
    }
    int q = idx - WIN_E - WDBC_E;
    if (q >= 0 && q < WOUT_E) {
        g_Woutb[q] = __float2bfloat16(wout[q]);
    }
}

// ---------------------------------------------------------------------------
// RMSNorm -> bf16 (norm_w folded into weights)
// ---------------------------------------------------------------------------
__global__ void rmsnorm_kernel(const float* __restrict__ x) {
    int t = blockIdx.x;
    int i = threadIdx.x;
    float v = x[(size_t)t * DMODEL + i];
    float ss = v * v;
    #pragma unroll
    for (int o = 16; o; o >>= 1) ss += __shfl_xor_sync(0xFFFFFFFFu, ss, o);
    __shared__ float red[8];
    if ((i & 31) == 0) red[i >> 5] = ss;
    __syncthreads();
    float tot = 0.f;
    #pragma unroll
    for (int j = 0; j < 8; j++) tot += red[j];
    float scale = rsqrtf(tot * (1.0f / DMODEL) + RMS_EPS);
    g_xnb[(size_t)t * DMODEL + i] = __float2bfloat16(v * scale);
}

// ---------------------------------------------------------------------------
// bf16 tensor-core GEMM: C[M,N] = A[M,K](bf16) * W[N,K](bf16)^T, fp32 accum.
// CTA tile 128x128x32, 8 warps, warp tile 64x32, mma.sync m16n8k16 bf16.
// 2-stage cp.async pipeline.
//  EPI 0: plain fp32 store                              -> in_proj
//  EPI 1: n<512 softplus(v+bias)->g_delta; 512..543 -> g_BC
//  EPI 2: v + resid -> C                                -> out_proj
// ---------------------------------------------------------------------------
#define GBM 128
#define GBN 128
#define GBK 32
#define LDA 40    // smem row stride in bf16 elements (80B, 16B aligned)

template<int EPI>
__global__ __launch_bounds__(256, 2)
void gemm_bf(const __nv_bfloat16* __restrict__ A,
             const __nv_bfloat16* __restrict__ W,
             float* __restrict__ C, int M, int N, int K,
             const float* __restrict__ bias,
             const float* __restrict__ resid) {
    __shared__ __nv_bfloat16 As[2][GBM * LDA];
    __shared__ __nv_bfloat16 Bs[2][GBN * LDA];

    const int tid  = threadIdx.x;
    const int m0   = blockIdx.y * GBM;
    const int n0   = blockIdx.x * GBN;
    const int lane = tid & 31;
    const int wid  = tid >> 5;
    const int wm   = wid & 1;          // warp row (2)
    const int wn   = wid >> 1;         // warp col (4)
    const int g    = lane >> 2;        // 0..7
    const int t4   = lane & 3;         // 0..3

    float acc[4][4][4];
    #pragma unroll
    for (int mf = 0; mf < 4; mf++)
        #pragma unroll
        for (int nf = 0; nf < 4; nf++)
            #pragma unroll
            for (int r = 0; r < 4; r++) acc[mf][nf][r] = 0.0f;

    // loader: per stage 1024 16B-chunks (512 A + 512 B), 4 per thread
    auto issue = [&](int stage, int k0) {
        #pragma unroll
        for (int i = 0; i < 4; i++) {
            int c    = tid + i * 256;
            int row  = (c >> 2) & 127;
            int part = (c & 3) * 8;            // bf16 elements (16B)
            const __nv_bfloat16* src;
            __nv_bfloat16* dstf;
            if (c < 512) {
                src  = A + (size_t)(m0 + row) * K + k0 + part;
                dstf = &As[stage][row * LDA + part];
            } else {
                src  = W + (size_t)(n0 + row) * K + k0 + part;
                dstf = &Bs[stage][row * LDA + part];
            }
            uint32_t dsts = (uint32_t)__cvta_generic_to_shared(dstf);
            CP_ASYNC16(dsts, src);
        }
        CP_COMMIT();
    };

    const int niter = K / GBK;
    issue(0, 0);

    for (int it = 0; it < niter; it++) {
        if (it + 1 < niter) {
            issue((it + 1) & 1, (it + 1) * GBK);
            asm volatile("cp.async.wait_group 1;");
        } else {
            asm volatile("cp.async.wait_group 0;");
        }
        __syncthreads();

        const __nv_bfloat16* as = As[it & 1];
        const __nv_bfloat16* bs = Bs[it & 1];

        #pragma unroll
        for (int kc = 0; kc < 2; kc++) {           // two k16 steps
            const int kk = kc * 16 + t4 * 2;
            uint32_t af[4][4], bf[4][2];
            #pragma unroll
            for (int mf = 0; mf < 4; mf++) {
                int bm = wm * 64 + mf * 16 + g;
                af[mf][0] = *(const uint32_t*)&as[bm * LDA + kk];
                af[mf][1] = *(const uint32_t*)&as[(bm + 8) * LDA + kk];
                af[mf][2] = *(const uint32_t*)&as[bm * LDA + kk + 8];
                af[mf][3] = *(const uint32_t*)&as[(bm + 8) * LDA + kk + 8];
            }
            #pragma unroll
            for (int nf = 0; nf < 4; nf++) {
                int bn = wn * 32 + nf * 8 + g;
                bf[nf][0] = *(const uint32_t*)&bs[bn * LDA + kk];
                bf[nf][1] = *(const uint32_t*)&bs[bn * LDA + kk + 8];
            }
            #pragma unroll
            for (int mf = 0; mf < 4; mf++)
                #pragma unroll
                for (int nf = 0; nf < 4; nf++)
                    mma_bf16(acc[mf][nf], af[mf], bf[nf]);
        }
        __syncthreads();
    }

    // Epilogue
    #pragma unroll
    for (int mf = 0; mf < 4; mf++) {
        #pragma unroll
        for (int nf = 0; nf < 4; nf++) {
            #pragma unroll
            for (int r = 0; r < 4; r++) {
                int t = m0 + wm * 64 + mf * 16 + g + ((r >> 1) ? 8 : 0);
                int n = n0 + wn * 32 + nf * 8 + t4 * 2 + (r & 1);
                float v = acc[mf][nf][r];
                if (EPI == 0) {
                    C[(size_t)t * N + n] = v;
                } else if (EPI == 1) {
                    if (n < 512) {
                        g_delta[(size_t)t * DINNER + n] = softplus_f(v + bias[n]);
                    } else if (n < 544) {
                        g_BC[(size_t)t * 32 + (n - 512)] = v;
                    }
                } else { // EPI == 2
                    C[(size_t)t * N + n] = v + resid[(size_t)t * N + n];
                }
            }
        }
    }
}

// ---------------------------------------------------------------------------
// Causal depthwise conv (width 4) + bias + SiLU; fp32 + bf16 outputs.
// ---------------------------------------------------------------------------
__global__ void conv_silu_kernel(const float* __restrict__ cw,
                                 const float* __restrict__ cb) {
    int q = blockIdx.x * blockDim.x + threadIdx.x;   // over (NTOK/8)*512
    if (q >= (NTOK / 8) * DINNER) return;
    int d  = q & 511;
    int t0 = (q >> 9) * 8;
    int l0 = t0 & (SEQL - 1);
    float w0 = cw[d * 4 + 0], w1 = cw[d * 4 + 1];
    float w2 = cw[d * 4 + 2], w3 = cw[d * 4 + 3];
    float b = cb[d];
    float xv[11];
    #pragma unroll
    for (int i = 0; i < 11; i++) {
        int li = l0 - 3 + i;
        xv[i] = (li >= 0) ? g_xz[(size_t)(t0 - 3 + i) * (2 * DINNER) + d] : 0.0f;
    }
    #pragma unroll
    for (int j = 0; j < 8; j++) {
        float a = fmaf(w3, xv[j + 3], fmaf(w2, xv[j + 2],
                  fmaf(w1, xv[j + 1], fmaf(w0, xv[j], b))));
        float s = silu_f(a);
        g_xc [(size_t)(t0 + j) * DINNER + d] = s;
        g_xcb[(size_t)(t0 + j) * DINNER + d] = __float2bfloat16(s);
    }
}

// ---------------------------------------------------------------------------
// Scan pass A: per-chunk end-state S; decay product P = exp2(A2 * sum delta).
// ---------------------------------------------------------------------------
__global__ void scan_phaseA(const float* __restrict__ A_log) {
    int d = blockIdx.x * 128 + threadIdx.x;
    int c = blockIdx.y;
    int b = blockIdx.z;

    float A2[NSTATE], h[NSTATE];
    #pragma unroll
    for (int n = 0; n < NSTATE; n++) {
        A2[n] = -__expf(A_log[d * NSTATE + n]) * 1.4426950408889634f;
        h[n] = 0.0f;
    }
    float sdl = 0.0f;
    int tbase = b * SEQL + c * CT;
    #pragma unroll 2
    for (int s = 0; s < CT; s++) {
        int t = tbase + s;
        float dl = g_delta[(size_t)t * DINNER + d];
        float xv = g_xc  [(size_t)t * DINNER + d];
        float xd = xv * dl;
        sdl += dl;
        const float4* bc = (const float4*)(g_BC + (size_t)t * 32);
        float4 b0 = bc[0], b1 = bc[1], b2 = bc[2], b3 = bc[3];
        float bvals[NSTATE] = {b0.x,b0.y,b0.z,b0.w, b1.x,b1.y,b1.z,b1.w,
                               b2.x,b2.y,b2.z,b2.w, b3.x,b3.y,b3.z,b3.w};
        #pragma unroll
        for (int n = 0; n < NSTATE; n++) {
            float dA = exp2f(dl * A2[n]);
            h[n] = fmaf(dA, h[n], xd * bvals[n]);
        }
    }
    size_t base = (((size_t)b * NCH + c) * NSTATE) * DINNER + d;
    #pragma unroll
    for (int n = 0; n < NSTATE; n++) {
        g_P[base + (size_t)n * DINNER] = exp2f(A2[n] * sdl);
        g_S[base + (size_t)n * DINNER] = h[n];
    }
}

// ---------------------------------------------------------------------------
// Scan pass B: sequential carry across chunks.
// ---------------------------------------------------------------------------
__global__ void scan_phaseB() {
    int idx = blockIdx.x * blockDim.x + threadIdx.x;
    if (idx >= BATCH * NSTATE * DINNER) return;
    int d = idx & 511;
    int n = (idx >> 9) & 15;
    int b = idx >> 13;
    float h = 0.0f;
    for (int c = 0; c < NCH; c++) {
        size_t o = (((size_t)b * NCH + c) * NSTATE + n) * DINNER + d;
        g_H[o] = h;
        h = fmaf(g_P[o], h, g_S[o]);
    }
}

// ---------------------------------------------------------------------------
// Scan pass C: rerun chunk with true initial state; +x*D, *silu(z); bf16 out.
// ---------------------------------------------------------------------------
__global__ void scan_phaseC(const float* __restrict__ A_log,
                            const float* __restrict__ Dw) {
    int d = blockIdx.x * 128 + threadIdx.x;
    int c = blockIdx.y;
    int b = blockIdx.z;

    float A2[NSTATE], h[NSTATE];
    size_t hbase = (((size_t)b * NCH + c) * NSTATE) * DINNER + d;
    #pragma unroll
    for (int n = 0; n < NSTATE; n++) {
        A2[n] = -__expf(A_log[d * NSTATE + n]) * 1.4426950408889634f;
        h[n] = g_H[hbase + (size_t)n * DINNER];
    }
    float Dd = Dw[d];
    int tbase = b * SEQL + c * CT;
    #pragma unroll 2
    for (int s = 0; s < CT; s++) {
        int t = tbase + s;
        float dl = g_delta[(size_t)t * DINNER + d];
        float xv = g_xc  [(size_t)t * DINNER + d];
        float xd = xv * dl;
        const float4* bc = (const float4*)(g_BC + (size_t)t * 32);
        float4 b0 = bc[0], b1 = bc[1], b2 = bc[2], b3 = bc[3];
        float4 c0 = bc[4], c1 = bc[5], c2 = bc[6], c3 = bc[7];
        float bvals[NSTATE] = {b0.x,b0.y,b0.z,b0.w, b1.x,b1.y,b1.z,b1.w,
                               b2.x,b2.y,b2.z,b2.w, b3.x,b3.y,b3.z,b3.w};
        float cvals[NSTATE] = {c0.x,c0.y,c0.z,c0.w, c1.x,c1.y,c1.z,c1.w,
                               c2.x,c2.y,c2.z,c2.w, c3.x,c3.y,c3.z,c3.w};
        float yv = 0.0f;
        #pragma unroll
        for (int n = 0; n < NSTATE; n++) {
            float dA = exp2f(dl * A2[n]);
            h[n] = fmaf(dA, h[n], xd * bvals[n]);
            yv = fmaf(h[n], cvals[n], yv);
        }
        float z = g_xz[(size_t)t * (2 * DINNER) + DINNER + d];
        g_yb[(size_t)t * DINNER + d] =
            __float2bfloat16((yv + xv * Dd) * silu_f(z));
    }
}

// ---------------------------------------------------------------------------
// Launch
// ---------------------------------------------------------------------------
extern "C" void kernel_launch(void* const* d_in, const int* in_sizes, int n_in,
                              void* d_out, int out_size) {
    const float* x          = (const float*)d_in[0];
    const float* norm_w     = (const float*)d_in[1];
    const float* in_proj_w  = (const float*)d_in[2];
    const float* conv_w     = (const float*)d_in[3];
    const float* conv_b     = (const float*)d_in[4];
    const float* A_log      = (const float*)d_in[5];
    const float* projB_w    = (const float*)d_in[6];
    const float* projC_w    = (const float*)d_in[7];
    const float* projDelta_w= (const float*)d_in[8];
    const float* projDelta_b= (const float*)d_in[9];
    const float* Dw         = (const float*)d_in[10];
    const float* out_proj_w = (const float*)d_in[11];
    float* out = (float*)d_out;

    __nv_bfloat16 *p_xnb, *p_xcb, *p_winb, *p_wdbcb, *p_woutb, *p_yb;
    float *p_xz;
    cudaGetSymbolAddress((void**)&p_xnb,   g_xnb);
    cudaGetSymbolAddress((void**)&p_xcb,   g_xcb);
    cudaGetSymbolAddress((void**)&p_winb,  g_Winb);
    cudaGetSymbolAddress((void**)&p_wdbcb, g_Wdbcb);
    cudaGetSymbolAddress((void**)&p_woutb, g_Woutb);
    cudaGetSymbolAddress((void**)&p_yb,    g_yb);
    cudaGetSymbolAddress((void**)&p_xz,    g_xz);

    // 1. weight prep (bf16 conversions; norm_w folded into in_proj weights)
    prep_w_kernel<<<(WIN_E + WDBC_E + WOUT_E + 255) / 256, 256>>>(
        in_proj_w, norm_w, projDelta_w, projB_w, projC_w, out_proj_w);

    // 2. RMSNorm -> bf16
    rmsnorm_kernel<<<NTOK, DMODEL>>>(x);

    // 3. in_proj: [8192,256]x[1024,256]^T -> g_xz (fp32)
    gemm_bf<0><<<dim3(2 * DINNER / GBN, NTOK / GBM), 256>>>(
        p_xnb, p_winb, p_xz, NTOK, 2 * DINNER, DMODEL, nullptr, nullptr);

    // 4. causal conv + silu
    conv_silu_kernel<<<((NTOK / 8) * DINNER + 255) / 256, 256>>>(conv_w, conv_b);

    // 5. delta/B/C projections: [8192,512]x[640,512]^T
    gemm_bf<1><<<dim3(NDBC / GBN, NTOK / GBM), 256>>>(
        p_xcb, p_wdbcb, nullptr, NTOK, NDBC, DINNER, projDelta_b, nullptr);

    // 6-8. chunked selective scan
    scan_phaseA<<<dim3(DINNER / 128, NCH, BATCH), 128>>>(A_log);
    scan_phaseB<<<(BATCH * NSTATE * DINNER + 255) / 256, 256>>>();
    scan_phaseC<<<dim3(DINNER / 128, NCH, BATCH), 128>>>(A_log, Dw);

    // 9. out_proj + residual: [8192,512]x[256,512]^T + x
    gemm_bf<2><<<dim3(DMODEL / GBN, NTOK / GBM), 256>>>(
        p_yb, p_woutb, out, NTOK, DMODEL, DINNER, nullptr, x);
}

// round 6
// speedup vs baseline: 3.3172x; 1.0378x over previous
#include <cuda_runtime.h>
#include <cuda_bf16.h>
#include <math.h>
#include <stdint.h>

// ---------------------------------------------------------------------------
// Problem constants
// ---------------------------------------------------------------------------
#define BATCH   4
#define SEQL    2048
#define DMODEL  256
#define DINNER  512
#define NSTATE  16
#define NTOK    (BATCH * SEQL)          // 8192
#define RMS_EPS 1.1920929e-07f

#define NCH     64                       // scan chunks
#define CT      (SEQL / NCH)             // 32 steps per chunk
#define NDBC    640                      // padded N for fused delta/B/C gemm

// ---------------------------------------------------------------------------
// Scratch (static device globals; no allocation allowed)
// ---------------------------------------------------------------------------
__device__ __nv_bfloat16 g_xnb  [(size_t)NTOK * DMODEL];      // rmsnorm (bf16)
__device__ __nv_bfloat16 g_xzb  [(size_t)NTOK * 2 * DINNER];  // x_branch|z bf16
__device__ __nv_bfloat16 g_xcb  [(size_t)NTOK * DINNER];      // conv+silu bf16
__device__ float         g_delta[(size_t)NTOK * DINNER];
__device__ float         g_BC   [(size_t)NTOK * 32];          // B(16) | C(16)
__device__ __nv_bfloat16 g_Winb [(size_t)(2 * DINNER) * DMODEL];
__device__ __nv_bfloat16 g_Wdbcb[(size_t)NDBC * DINNER];
__device__ __nv_bfloat16 g_Woutb[(size_t)DMODEL * DINNER];
__device__ __nv_bfloat16 g_yb   [(size_t)NTOK * DINNER];
__device__ float g_sdl[(size_t)BATCH * NCH * DINNER];          // per-chunk sum(delta)
__device__ float g_S  [(size_t)BATCH * NCH * NSTATE * DINNER];
__device__ float g_H  [(size_t)BATCH * NCH * NSTATE * DINNER];

// ---------------------------------------------------------------------------
// Helpers
// ---------------------------------------------------------------------------
__device__ __forceinline__ float silu_f(float v) { return v / (1.0f + __expf(-v)); }
__device__ __forceinline__ float softplus_f(float v) {
    return (v > 20.0f) ? v : log1pf(__expf(v));
}
__device__ __forceinline__ void mma_bf16(float (&d)[4], const uint32_t (&a)[4],
                                         const uint32_t (&b)[2]) {
    asm volatile(
        "mma.sync.aligned.m16n8k16.row.col.f32.bf16.bf16.f32 "
        "{%0,%1,%2,%3},{%4,%5,%6,%7},{%8,%9},{%0,%1,%2,%3};"
        : "+f"(d[0]), "+f"(d[1]), "+f"(d[2]), "+f"(d[3])
        : "r"(a[0]), "r"(a[1]), "r"(a[2]), "r"(a[3]), "r"(b[0]), "r"(b[1]));
}
#define LDSM_X4(r0, r1, r2, r3, addr)                                        \
    asm volatile("ldmatrix.sync.aligned.m8n8.x4.shared.b16 {%0,%1,%2,%3}, [%4];" \
                 : "=r"(r0), "=r"(r1), "=r"(r2), "=r"(r3) : "r"(addr))
#define CP_ASYNC16(dst, src) \
    asm volatile("cp.async.cg.shared.global [%0], [%1], 16;" :: "r"(dst), "l"(src))
#define CP_COMMIT() asm volatile("cp.async.commit_group;")

// ---------------------------------------------------------------------------
// Weight prep: bf16 conversions (+ norm_w folded into in_proj weights)
// ---------------------------------------------------------------------------
#define WIN_E  (2 * DINNER * DMODEL)    // 262144
#define WDBC_E (NDBC * DINNER)          // 327680
#define WOUT_E (DMODEL * DINNER)        // 131072
__global__ void prep_w_kernel(const float* __restrict__ win,
                              const float* __restrict__ normw,
                              const float* __restrict__ wd,
                              const float* __restrict__ wb,
                              const float* __restrict__ wc,
                              const float* __restrict__ wout) {
    int idx = blockIdx.x * blockDim.x + threadIdx.x;
    if (idx < WIN_E) {
        int k = idx & (DMODEL - 1);
        g_Winb[idx] = __float2bfloat16(win[idx] * normw[k]);
    }
    int j = idx - WIN_E;
    if (j >= 0 && j < WDBC_E) {
        int r = j / DINNER;
        int k = j - r * DINNER;
        float v;
        if      (r < 512) v = wd[(size_t)r * DINNER + k];
        else if (r < 528) v = wb[(size_t)(r - 512) * DINNER + k];
        else if (r < 544) v = wc[(size_t)(r - 528) * DINNER + k];
        else              v = 0.0f;
        g_Wdbcb[j] = __float2bfloat16(v);
    }
    int q = idx - WIN_E - WDBC_E;
    if (q >= 0 && q < WOUT_E) {
        g_Woutb[q] = __float2bfloat16(wout[q]);
    }
}

// ---------------------------------------------------------------------------
// RMSNorm -> bf16 (norm_w folded into weights)
// ---------------------------------------------------------------------------
__global__ void rmsnorm_kernel(const float* __restrict__ x) {
    int t = blockIdx.x;
    int i = threadIdx.x;
    float v = x[(size_t)t * DMODEL + i];
    float ss = v * v;
    #pragma unroll
    for (int o = 16; o; o >>= 1) ss += __shfl_xor_sync(0xFFFFFFFFu, ss, o);
    __shared__ float red[8];
    if ((i & 31) == 0) red[i >> 5] = ss;
    __syncthreads();
    float tot = 0.f;
    #pragma unroll
    for (int j = 0; j < 8; j++) tot += red[j];
    float scale = rsqrtf(tot * (1.0f / DMODEL) + RMS_EPS);
    g_xnb[(size_t)t * DMODEL + i] = __float2bfloat16(v * scale);
}

// ---------------------------------------------------------------------------
// bf16 tensor-core GEMM: C[M,N] = A[M,K](bf16) * W[N,K](bf16)^T, fp32 accum.
// CTA tile 128x128x32, 8 warps, warp tile 64x32, mma m16n8k16 bf16, ldmatrix,
// 3-stage cp.async pipeline (dynamic smem).
//  EPI 0: bf16 store (-> g_xzb)
//  EPI 1: n<512 softplus(v+bias)->g_delta; 512..543 -> g_BC
//  EPI 2: fp32 v + resid -> Cf (out_proj)
// ---------------------------------------------------------------------------
#define GBM 128
#define GBN 128
#define GBK 32
#define LDA 40                               // bf16 elems; 80B row stride
#define ATILE_B (GBM * LDA * 2)              // 10240
#define STAGE_B (2 * ATILE_B)                // 20480
#define GSMEM   (3 * STAGE_B)                // 61440

template<int EPI>
__global__ __launch_bounds__(256, 2)
void gemm_bf(const __nv_bfloat16* __restrict__ A,
             const __nv_bfloat16* __restrict__ W,
             float* __restrict__ Cf, __nv_bfloat16* __restrict__ Cb,
             int M, int N, int K,
             const float* __restrict__ bias,
             const float* __restrict__ resid) {
    extern __shared__ __align__(128) char dsm[];
    const uint32_t sbase = (uint32_t)__cvta_generic_to_shared(dsm);

    const int tid  = threadIdx.x;
    const int m0   = blockIdx.y * GBM;
    const int n0   = blockIdx.x * GBN;
    const int lane = tid & 31;
    const int wid  = tid >> 5;
    const int wm   = wid & 1;          // warp row (2)
    const int wn   = wid >> 1;         // warp col (4)
    const int g    = lane >> 2;        // 0..7
    const int t4   = lane & 3;         // 0..3

    float acc[4][4][4];
    #pragma unroll
    for (int mf = 0; mf < 4; mf++)
        #pragma unroll
        for (int nf = 0; nf < 4; nf++)
            #pragma unroll
            for (int r = 0; r < 4; r++) acc[mf][nf][r] = 0.0f;

    // per-lane ldmatrix source offsets (bytes, within a stage's A / B tile)
    const uint32_t aoff =
        ((uint32_t)(wm * 64 + (lane & 15)) * LDA + ((lane >> 4) << 3)) * 2;
    const uint32_t boff =
        ((uint32_t)(wn * 32 + (lane & 7) + ((lane & 16) ? 8 : 0)) * LDA +
         (((lane >> 3) & 1) << 3)) * 2;

    auto issue = [&](int it) {
        const int stage = it % 3;
        const uint32_t ab = sbase + stage * STAGE_B;
        const uint32_t bb = ab + ATILE_B;
        const int k0 = it * GBK;
        #pragma unroll
        for (int i = 0; i < 4; i++) {
            int c    = tid + i * 256;
            int row  = (c >> 2) & 127;
            int part = (c & 3) * 8;            // bf16 elems (16B chunk)
            if (c < 512) {
                CP_ASYNC16(ab + (uint32_t)(row * LDA + part) * 2,
                           A + (size_t)(m0 + row) * K + k0 + part);
            } else {
                CP_ASYNC16(bb + (uint32_t)(row * LDA + part) * 2,
                           W + (size_t)(n0 + row) * K + k0 + part);
            }
        }
        CP_COMMIT();
    };

    const int niter = K / GBK;
    issue(0); issue(1);
    asm volatile("cp.async.wait_group 1;");
    __syncthreads();

    for (int it = 0; it < niter; it++) {
        if (it + 2 < niter) issue(it + 2);

        const int stage = it % 3;
        const uint32_t aA = sbase + stage * STAGE_B + aoff;
        const uint32_t aB = sbase + stage * STAGE_B + ATILE_B + boff;

        #pragma unroll
        for (int kc = 0; kc < 2; kc++) {          // two k16 steps (32B offset)
            uint32_t af[4][4], bf[4][2];
            #pragma unroll
            for (int mf = 0; mf < 4; mf++) {
                LDSM_X4(af[mf][0], af[mf][1], af[mf][2], af[mf][3],
                        aA + (uint32_t)(mf * 16 * LDA * 2 + kc * 32));
            }
            #pragma unroll
            for (int nfp = 0; nfp < 2; nfp++) {
                LDSM_X4(bf[2 * nfp][0], bf[2 * nfp][1],
                        bf[2 * nfp + 1][0], bf[2 * nfp + 1][1],
                        aB + (uint32_t)(nfp * 16 * LDA * 2 + kc * 32));
            }
            #pragma unroll
            for (int mf = 0; mf < 4; mf++)
                #pragma unroll
                for (int nf = 0; nf < 4; nf++)
                    mma_bf16(acc[mf][nf], af[mf], bf[nf]);
        }

        if (it + 1 < niter) {
            if (it + 2 < niter) asm volatile("cp.async.wait_group 1;");
            else                asm volatile("cp.async.wait_group 0;");
            __syncthreads();
        }
    }

    // Epilogue
    #pragma unroll
    for (int mf = 0; mf < 4; mf++) {
        #pragma unroll
        for (int nf = 0; nf < 4; nf++) {
            #pragma unroll
            for (int r = 0; r < 4; r++) {
                int t = m0 + wm * 64 + mf * 16 + g + ((r >> 1) ? 8 : 0);
                int n = n0 + wn * 32 + nf * 8 + t4 * 2 + (r & 1);
                float v = acc[mf][nf][r];
                if (EPI == 0) {
                    Cb[(size_t)t * N + n] = __float2bfloat16(v);
                } else if (EPI == 1) {
                    if (n < 512) {
                        g_delta[(size_t)t * DINNER + n] = softplus_f(v + bias[n]);
                    } else if (n < 544) {
                        g_BC[(size_t)t * 32 + (n - 512)] = v;
                    }
                } else { // EPI == 2
                    Cf[(size_t)t * N + n] = v + resid[(size_t)t * N + n];
                }
            }
        }
    }
}

// ---------------------------------------------------------------------------
// Causal depthwise conv (width 4) + bias + SiLU; bf16 in (g_xzb), bf16 out.
// ---------------------------------------------------------------------------
__global__ void conv_silu_kernel(const float* __restrict__ cw,
                                 const float* __restrict__ cb) {
    int q = blockIdx.x * blockDim.x + threadIdx.x;   // over (NTOK/8)*512
    if (q >= (NTOK / 8) * DINNER) return;
    int d  = q & 511;
    int t0 = (q >> 9) * 8;
    int l0 = t0 & (SEQL - 1);
    float w0 = cw[d * 4 + 0], w1 = cw[d * 4 + 1];
    float w2 = cw[d * 4 + 2], w3 = cw[d * 4 + 3];
    float b = cb[d];
    float xv[11];
    #pragma unroll
    for (int i = 0; i < 11; i++) {
        int li = l0 - 3 + i;
        xv[i] = (li >= 0)
            ? __bfloat162float(g_xzb[(size_t)(t0 - 3 + i) * (2 * DINNER) + d])
            : 0.0f;
    }
    #pragma unroll
    for (int j = 0; j < 8; j++) {
        float a = fmaf(w3, xv[j + 3], fmaf(w2, xv[j + 2],
                  fmaf(w1, xv[j + 1], fmaf(w0, xv[j], b))));
        g_xcb[(size_t)(t0 + j) * DINNER + d] = __float2bfloat16(silu_f(a));
    }
}

// ---------------------------------------------------------------------------
// Scan pass A: per-chunk end-state S and sum(delta).
// ---------------------------------------------------------------------------
__global__ void scan_phaseA(const float* __restrict__ A_log) {
    int d = blockIdx.x * 128 + threadIdx.x;
    int c = blockIdx.y;
    int b = blockIdx.z;

    float A2[NSTATE], h[NSTATE];
    #pragma unroll
    for (int n = 0; n < NSTATE; n++) {
        A2[n] = -__expf(A_log[d * NSTATE + n]) * 1.4426950408889634f;
        h[n] = 0.0f;
    }
    float sdl = 0.0f;
    int tbase = b * SEQL + c * CT;
    #pragma unroll 2
    for (int s = 0; s < CT; s++) {
        int t = tbase + s;
        float dl = g_delta[(size_t)t * DINNER + d];
        float xv = __bfloat162float(g_xcb[(size_t)t * DINNER + d]);
        float xd = xv * dl;
        sdl += dl;
        const float4* bc = (const float4*)(g_BC + (size_t)t * 32);
        float4 b0 = bc[0], b1 = bc[1], b2 = bc[2], b3 = bc[3];
        float bvals[NSTATE] = {b0.x,b0.y,b0.z,b0.w, b1.x,b1.y,b1.z,b1.w,
                               b2.x,b2.y,b2.z,b2.w, b3.x,b3.y,b3.z,b3.w};
        #pragma unroll
        for (int n = 0; n < NSTATE; n++) {
            float dA = exp2f(dl * A2[n]);
            h[n] = fmaf(dA, h[n], xd * bvals[n]);
        }
    }
    g_sdl[((size_t)b * NCH + c) * DINNER + d] = sdl;
    size_t base = (((size_t)b * NCH + c) * NSTATE) * DINNER + d;
    #pragma unroll
    for (int n = 0; n < NSTATE; n++)
        g_S[base + (size_t)n * DINNER] = h[n];
}

// ---------------------------------------------------------------------------
// Scan pass B: sequential carry; P recomputed from sum(delta).
// ---------------------------------------------------------------------------
__global__ void scan_phaseB(const float* __restrict__ A_log) {
    int idx = blockIdx.x * blockDim.x + threadIdx.x;
    if (idx >= BATCH * NSTATE * DINNER) return;
    int d = idx & 511;
    int n = (idx >> 9) & 15;
    int b = idx >> 13;
    float A2 = -__expf(A_log[d * NSTATE + n]) * 1.4426950408889634f;
    float h = 0.0f;
    for (int c = 0; c < NCH; c++) {
        size_t o = (((size_t)b * NCH + c) * NSTATE + n) * DINNER + d;
        g_H[o] = h;
        float P = exp2f(A2 * g_sdl[((size_t)b * NCH + c) * DINNER + d]);
        h = fmaf(P, h, g_S[o]);
    }
}

// ---------------------------------------------------------------------------
// Scan pass C: rerun chunk with true initial state; +x*D, *silu(z); bf16 out.
// ---------------------------------------------------------------------------
__global__ void scan_phaseC(const float* __restrict__ A_log,
                            const float* __restrict__ Dw) {
    int d = blockIdx.x * 128 + threadIdx.x;
    int c = blockIdx.y;
    int b = blockIdx.z;

    float A2[NSTATE], h[NSTATE];
    size_t hbase = (((size_t)b * NCH + c) * NSTATE) * DINNER + d;
    #pragma unroll
    for (int n = 0; n < NSTATE; n++) {
        A2[n] = -__expf(A_log[d * NSTATE + n]) * 1.4426950408889634f;
        h[n] = g_H[hbase + (size_t)n * DINNER];
    }
    float Dd = Dw[d];
    int tbase = b * SEQL + c * CT;
    #pragma unroll 2
    for (int s = 0; s < CT; s++) {
        int t = tbase + s;
        float dl = g_delta[(size_t)t * DINNER + d];
        float xv = __bfloat162float(g_xcb[(size_t)t * DINNER + d]);
        float xd = xv * dl;
        const float4* bc = (const float4*)(g_BC + (size_t)t * 32);
        float4 b0 = bc[0], b1 = bc[1], b2 = bc[2], b3 = bc[3];
        float4 c0 = bc[4], c1 = bc[5], c2 = bc[6], c3 = bc[7];
        float bvals[NSTATE] = {b0.x,b0.y,b0.z,b0.w, b1.x,b1.y,b1.z,b1.w,
                               b2.x,b2.y,b2.z,b2.w, b3.x,b3.y,b3.z,b3.w};
        float cvals[NSTATE] = {c0.x,c0.y,c0.z,c0.w, c1.x,c1.y,c1.z,c1.w,
                               c2.x,c2.y,c2.z,c2.w, c3.x,c3.y,c3.z,c3.w};
        float yv = 0.0f;
        #pragma unroll
        for (int n = 0; n < NSTATE; n++) {
            float dA = exp2f(dl * A2[n]);
            h[n] = fmaf(dA, h[n], xd * bvals[n]);
            yv = fmaf(h[n], cvals[n], yv);
        }
        float z = __bfloat162float(g_xzb[(size_t)t * (2 * DINNER) + DINNER + d]);
        g_yb[(size_t)t * DINNER + d] =
            __float2bfloat16((yv + xv * Dd) * silu_f(z));
    }
}

// ---------------------------------------------------------------------------
// Launch
// ---------------------------------------------------------------------------
extern "C" void kernel_launch(void* const* d_in, const int* in_sizes, int n_in,
                              void* d_out, int out_size) {
    const float* x          = (const float*)d_in[0];
    const float* norm_w     = (const float*)d_in[1];
    const float* in_proj_w  = (const float*)d_in[2];
    const float* conv_w     = (const float*)d_in[3];
    const float* conv_b     = (const float*)d_in[4];
    const float* A_log      = (const float*)d_in[5];
    const float* projB_w    = (const float*)d_in[6];
    const float* projC_w    = (const float*)d_in[7];
    const float* projDelta_w= (const float*)d_in[8];
    const float* projDelta_b= (const float*)d_in[9];
    const float* Dw         = (const float*)d_in[10];
    const float* out_proj_w = (const float*)d_in[11];
    float* out = (float*)d_out;

    __nv_bfloat16 *p_xnb, *p_xzb, *p_xcb, *p_winb, *p_wdbcb, *p_woutb, *p_yb;
    cudaGetSymbolAddress((void**)&p_xnb,   g_xnb);
    cudaGetSymbolAddress((void**)&p_xzb,   g_xzb);
    cudaGetSymbolAddress((void**)&p_xcb,   g_xcb);
    cudaGetSymbolAddress((void**)&p_winb,  g_Winb);
    cudaGetSymbolAddress((void**)&p_wdbcb, g_Wdbcb);
    cudaGetSymbolAddress((void**)&p_woutb, g_Woutb);
    cudaGetSymbolAddress((void**)&p_yb,    g_yb);

    cudaFuncSetAttribute(gemm_bf<0>, cudaFuncAttributeMaxDynamicSharedMemorySize, GSMEM);
    cudaFuncSetAttribute(gemm_bf<1>, cudaFuncAttributeMaxDynamicSharedMemorySize, GSMEM);
    cudaFuncSetAttribute(gemm_bf<2>, cudaFuncAttributeMaxDynamicSharedMemorySize, GSMEM);

    // 1. weight prep
    prep_w_kernel<<<(WIN_E + WDBC_E + WOUT_E + 255) / 256, 256>>>(
        in_proj_w, norm_w, projDelta_w, projB_w, projC_w, out_proj_w);

    // 2. RMSNorm -> bf16
    rmsnorm_kernel<<<NTOK, DMODEL>>>(x);

    // 3. in_proj: [8192,256]x[1024,256]^T -> g_xzb (bf16)
    gemm_bf<0><<<dim3(2 * DINNER / GBN, NTOK / GBM), 256, GSMEM>>>(
        p_xnb, p_winb, nullptr, p_xzb, NTOK, 2 * DINNER, DMODEL, nullptr, nullptr);

    // 4. causal conv + silu
    conv_silu_kernel<<<((NTOK / 8) * DINNER + 255) / 256, 256>>>(conv_w, conv_b);

    // 5. delta/B/C projections: [8192,512]x[640,512]^T
    gemm_bf<1><<<dim3(NDBC / GBN, NTOK / GBM), 256, GSMEM>>>(
        p_xcb, p_wdbcb, nullptr, nullptr, NTOK, NDBC, DINNER, projDelta_b, nullptr);

    // 6-8. chunked selective scan
    scan_phaseA<<<dim3(DINNER / 128, NCH, BATCH), 128>>>(A_log);
    scan_phaseB<<<(BATCH * NSTATE * DINNER + 255) / 256, 256>>>(A_log);
    scan_phaseC<<<dim3(DINNER / 128, NCH, BATCH), 128>>>(A_log, Dw);

    // 9. out_proj + residual: [8192,512]x[256,512]^T + x
    gemm_bf<2><<<dim3(DMODEL / GBN, NTOK / GBM), 256, GSMEM>>>(
        p_yb, p_woutb, out, nullptr, NTOK, DMODEL, DINNER, nullptr, x);
}

// round 7
// speedup vs baseline: 3.4048x; 1.0264x over previous
#include <cuda_runtime.h>
#include <cuda_bf16.h>
#include <math.h>
#include <stdint.h>

// ---------------------------------------------------------------------------
// Problem constants
// ---------------------------------------------------------------------------
#define BATCH   4
#define SEQL    2048
#define DMODEL  256
#define DINNER  512
#define NSTATE  16
#define NTOK    (BATCH * SEQL)          // 8192
#define RMS_EPS 1.1920929e-07f

#define NCH     64                       // scan chunks
#define CT      (SEQL / NCH)             // 32 steps per chunk
#define NDBC    640                      // padded N for fused delta/B/C gemm

// ---------------------------------------------------------------------------
// Scratch (static device globals; no allocation allowed)
// ---------------------------------------------------------------------------
__device__ __nv_bfloat16 g_xnb  [(size_t)NTOK * DMODEL];      // rmsnorm (bf16)
__device__ __nv_bfloat16 g_xzb  [(size_t)NTOK * 2 * DINNER];  // x_branch|z bf16
__device__ __nv_bfloat16 g_xcb  [(size_t)NTOK * DINNER];      // conv+silu bf16
__device__ float         g_delta[(size_t)NTOK * DINNER];
__device__ float         g_BC   [(size_t)NTOK * 32];          // B(16) | C(16)
__device__ __nv_bfloat16 g_Winb [(size_t)(2 * DINNER) * DMODEL];
__device__ __nv_bfloat16 g_Wdbcb[(size_t)NDBC * DINNER];
__device__ __nv_bfloat16 g_Woutb[(size_t)DMODEL * DINNER];
__device__ __nv_bfloat16 g_yb   [(size_t)NTOK * DINNER];
__device__ float g_sdl[(size_t)BATCH * NCH * DINNER];          // per-chunk sum(delta)
__device__ float g_S  [(size_t)BATCH * NCH * NSTATE * DINNER];
__device__ float g_H  [(size_t)BATCH * NCH * NSTATE * DINNER];

// ---------------------------------------------------------------------------
// Helpers
// ---------------------------------------------------------------------------
__device__ __forceinline__ float silu_f(float v) { return v / (1.0f + __expf(-v)); }
__device__ __forceinline__ float softplus_f(float v) {
    return (v > 20.0f) ? v : log1pf(__expf(v));
}
__device__ __forceinline__ void mma_bf16(float (&d)[4], const uint32_t (&a)[4],
                                         const uint32_t (&b)[2]) {
    asm volatile(
        "mma.sync.aligned.m16n8k16.row.col.f32.bf16.bf16.f32 "
        "{%0,%1,%2,%3},{%4,%5,%6,%7},{%8,%9},{%0,%1,%2,%3};"
        : "+f"(d[0]), "+f"(d[1]), "+f"(d[2]), "+f"(d[3])
        : "r"(a[0]), "r"(a[1]), "r"(a[2]), "r"(a[3]), "r"(b[0]), "r"(b[1]));
}
#define LDSM_X4(r0, r1, r2, r3, addr)                                        \
    asm volatile("ldmatrix.sync.aligned.m8n8.x4.shared.b16 {%0,%1,%2,%3}, [%4];" \
                 : "=r"(r0), "=r"(r1), "=r"(r2), "=r"(r3) : "r"(addr))
#define CP_ASYNC16(dst, src) \
    asm volatile("cp.async.cg.shared.global [%0], [%1], 16;" :: "r"(dst), "l"(src))
#define CP_COMMIT() asm volatile("cp.async.commit_group;")

// ---------------------------------------------------------------------------
// Weight prep: bf16 conversions (+ norm_w folded into in_proj weights)
// ---------------------------------------------------------------------------
#define WIN_E  (2 * DINNER * DMODEL)    // 262144
#define WDBC_E (NDBC * DINNER)          // 327680
#define WOUT_E (DMODEL * DINNER)        // 131072
__global__ void prep_w_kernel(const float* __restrict__ win,
                              const float* __restrict__ normw,
                              const float* __restrict__ wd,
                              const float* __restrict__ wb,
                              const float* __restrict__ wc,
                              const float* __restrict__ wout) {
    int idx = blockIdx.x * blockDim.x + threadIdx.x;
    if (idx < WIN_E) {
        int k = idx & (DMODEL - 1);
        g_Winb[idx] = __float2bfloat16(win[idx] * normw[k]);
    }
    int j = idx - WIN_E;
    if (j >= 0 && j < WDBC_E) {
        int r = j / DINNER;
        int k = j - r * DINNER;
        float v;
        if      (r < 512) v = wd[(size_t)r * DINNER + k];
        else if (r < 528) v = wb[(size_t)(r - 512) * DINNER + k];
        else if (r < 544) v = wc[(size_t)(r - 528) * DINNER + k];
        else              v = 0.0f;
        g_Wdbcb[j] = __float2bfloat16(v);
    }
    int q = idx - WIN_E - WDBC_E;
    if (q >= 0 && q < WOUT_E) {
        g_Woutb[q] = __float2bfloat16(wout[q]);
    }
}

// ---------------------------------------------------------------------------
// RMSNorm -> bf16 (norm_w folded into weights)
// ---------------------------------------------------------------------------
__global__ void rmsnorm_kernel(const float* __restrict__ x) {
    int t = blockIdx.x;
    int i = threadIdx.x;
    float v = x[(size_t)t * DMODEL + i];
    float ss = v * v;
    #pragma unroll
    for (int o = 16; o; o >>= 1) ss += __shfl_xor_sync(0xFFFFFFFFu, ss, o);
    __shared__ float red[8];
    if ((i & 31) == 0) red[i >> 5] = ss;
    __syncthreads();
    float tot = 0.f;
    #pragma unroll
    for (int j = 0; j < 8; j++) tot += red[j];
    float scale = rsqrtf(tot * (1.0f / DMODEL) + RMS_EPS);
    g_xnb[(size_t)t * DMODEL + i] = __float2bfloat16(v * scale);
}

// ---------------------------------------------------------------------------
// bf16 tensor-core GEMM: C[M,N] = A[M,K](bf16) * W[N,K](bf16)^T, fp32 accum.
// CTA tile 128x64x32, 128 threads (4 warps), warp tile 64x32, ldmatrix,
// mma m16n8k16, 3-stage cp.async. Small CTA => ~4 CTA/SM, fine-grained waves.
//  EPI 0: bf16 store (-> g_xzb)
//  EPI 1: n<512 softplus(v+bias)->g_delta; 512..543 -> g_BC
//  EPI 2: fp32 v + resid -> Cf (out_proj)
// ---------------------------------------------------------------------------
#define GBM 128
#define GBN 64
#define GBK 32
#define LDA 40                               // bf16 elems; 80B row stride
#define ATILE_B (GBM * LDA * 2)              // 10240
#define BTILE_B (GBN * LDA * 2)              // 5120
#define STAGE_B (ATILE_B + BTILE_B)          // 15360
#define GSMEM   (3 * STAGE_B)                // 46080

template<int EPI>
__global__ __launch_bounds__(128, 4)
void gemm_bf(const __nv_bfloat16* __restrict__ A,
             const __nv_bfloat16* __restrict__ W,
             float* __restrict__ Cf, __nv_bfloat16* __restrict__ Cb,
             int M, int N, int K,
             const float* __restrict__ bias,
             const float* __restrict__ resid) {
    extern __shared__ __align__(128) char dsm[];
    const uint32_t sbase = (uint32_t)__cvta_generic_to_shared(dsm);

    const int tid  = threadIdx.x;
    const int m0   = blockIdx.y * GBM;
    const int n0   = blockIdx.x * GBN;
    const int lane = tid & 31;
    const int wid  = tid >> 5;
    const int wm   = wid & 1;          // warp row (2)
    const int wn   = wid >> 1;         // warp col (2)
    const int g    = lane >> 2;        // 0..7
    const int t4   = lane & 3;         // 0..3

    float acc[4][4][4];
    #pragma unroll
    for (int mf = 0; mf < 4; mf++)
        #pragma unroll
        for (int nf = 0; nf < 4; nf++)
            #pragma unroll
            for (int r = 0; r < 4; r++) acc[mf][nf][r] = 0.0f;

    // per-lane ldmatrix source offsets (bytes, within a stage's A / B tile)
    const uint32_t aoff =
        ((uint32_t)(wm * 64 + (lane & 15)) * LDA + ((lane >> 4) << 3)) * 2;
    const uint32_t boff =
        ((uint32_t)(wn * 32 + (lane & 7) + ((lane & 16) ? 8 : 0)) * LDA +
         (((lane >> 3) & 1) << 3)) * 2;

    // loader: 768 16B-chunks per stage (512 A rows-chunks + 256 B), 6/thread
    auto issue = [&](int it) {
        const int stage = it % 3;
        const uint32_t ab = sbase + stage * STAGE_B;
        const uint32_t bb = ab + ATILE_B;
        const int k0 = it * GBK;
        #pragma unroll
        for (int i = 0; i < 6; i++) {
            int c    = tid + i * 128;
            int part = (c & 3) * 8;            // bf16 elems (16B chunk)
            if (c < 512) {
                int row = c >> 2;              // 0..127
                CP_ASYNC16(ab + (uint32_t)(row * LDA + part) * 2,
                           A + (size_t)(m0 + row) * K + k0 + part);
            } else {
                int row = (c - 512) >> 2;      // 0..63
                CP_ASYNC16(bb + (uint32_t)(row * LDA + part) * 2,
                           W + (size_t)(n0 + row) * K + k0 + part);
            }
        }
        CP_COMMIT();
    };

    const int niter = K / GBK;
    issue(0); issue(1);
    asm volatile("cp.async.wait_group 1;");
    __syncthreads();

    for (int it = 0; it < niter; it++) {
        if (it + 2 < niter) issue(it + 2);

        const int stage = it % 3;
        const uint32_t aA = sbase + stage * STAGE_B + aoff;
        const uint32_t aB = sbase + stage * STAGE_B + ATILE_B + boff;

        #pragma unroll
        for (int kc = 0; kc < 2; kc++) {          // two k16 steps (32B offset)
            uint32_t af[4][4], bf[4][2];
            #pragma unroll
            for (int mf = 0; mf < 4; mf++) {
                LDSM_X4(af[mf][0], af[mf][1], af[mf][2], af[mf][3],
                        aA + (uint32_t)(mf * 16 * LDA * 2 + kc * 32));
            }
            #pragma unroll
            for (int nfp = 0; nfp < 2; nfp++) {
                LDSM_X4(bf[2 * nfp][0], bf[2 * nfp][1],
                        bf[2 * nfp + 1][0], bf[2 * nfp + 1][1],
                        aB + (uint32_t)(nfp * 16 * LDA * 2 + kc * 32));
            }
            #pragma unroll
            for (int mf = 0; mf < 4; mf++)
                #pragma unroll
                for (int nf = 0; nf < 4; nf++)
                    mma_bf16(acc[mf][nf], af[mf], bf[nf]);
        }

        if (it + 1 < niter) {
            if (it + 2 < niter) asm volatile("cp.async.wait_group 1;");
            else                asm volatile("cp.async.wait_group 0;");
            __syncthreads();
        }
    }

    // Epilogue
    #pragma unroll
    for (int mf = 0; mf < 4; mf++) {
        #pragma unroll
        for (int nf = 0; nf < 4; nf++) {
            #pragma unroll
            for (int r = 0; r < 4; r++) {
                int t = m0 + wm * 64 + mf * 16 + g + ((r >> 1) ? 8 : 0);
                int n = n0 + wn * 32 + nf * 8 + t4 * 2 + (r & 1);
                float v = acc[mf][nf][r];
                if (EPI == 0) {
                    Cb[(size_t)t * N + n] = __float2bfloat16(v);
                } else if (EPI == 1) {
                    if (n < 512) {
                        g_delta[(size_t)t * DINNER + n] = softplus_f(v + bias[n]);
                    } else if (n < 544) {
                        g_BC[(size_t)t * 32 + (n - 512)] = v;
                    }
                } else { // EPI == 2
                    Cf[(size_t)t * N + n] = v + resid[(size_t)t * N + n];
                }
            }
        }
    }
}

// ---------------------------------------------------------------------------
// Causal depthwise conv (width 4) + bias + SiLU; bf16 in/out.
// Each thread: 2 adjacent channels x 4 timesteps (packed u32 loads/stores).
// ---------------------------------------------------------------------------
__global__ void conv_silu_kernel(const float* __restrict__ cw,
                                 const float* __restrict__ cb) {
    int q = blockIdx.x * blockDim.x + threadIdx.x;   // over (NTOK/4)*(DINNER/2)
    if (q >= (NTOK / 4) * (DINNER / 2)) return;
    int dp = (q & 255) * 2;                          // channel pair base
    int t0 = (q >> 8) * 4;
    int l0 = t0 & (SEQL - 1);
    float w0a = cw[dp * 4 + 0], w1a = cw[dp * 4 + 1];
    float w2a = cw[dp * 4 + 2], w3a = cw[dp * 4 + 3];
    float w0b = cw[dp * 4 + 4], w1b = cw[dp * 4 + 5];
    float w2b = cw[dp * 4 + 6], w3b = cw[dp * 4 + 7];
    float ba = cb[dp], bb = cb[dp + 1];
    float xa[7], xb[7];
    #pragma unroll
    for (int i = 0; i < 7; i++) {
        int li = l0 - 3 + i;
        if (li >= 0) {
            __nv_bfloat162 v = *(const __nv_bfloat162*)
                &g_xzb[(size_t)(t0 - 3 + i) * (2 * DINNER) + dp];
            xa[i] = __bfloat162float(v.x);
            xb[i] = __bfloat162float(v.y);
        } else { xa[i] = 0.0f; xb[i] = 0.0f; }
    }
    #pragma unroll
    for (int j = 0; j < 4; j++) {
        float va = fmaf(w3a, xa[j + 3], fmaf(w2a, xa[j + 2],
                   fmaf(w1a, xa[j + 1], fmaf(w0a, xa[j], ba))));
        float vb = fmaf(w3b, xb[j + 3], fmaf(w2b, xb[j + 2],
                   fmaf(w1b, xb[j + 1], fmaf(w0b, xb[j], bb))));
        __nv_bfloat162 o;
        o.x = __float2bfloat16(silu_f(va));
        o.y = __float2bfloat16(silu_f(vb));
        *(__nv_bfloat162*)&g_xcb[(size_t)(t0 + j) * DINNER + dp] = o;
    }
}

// ---------------------------------------------------------------------------
// Scan pass A: per-chunk end-state S and sum(delta).
// ---------------------------------------------------------------------------
__global__ void scan_phaseA(const float* __restrict__ A_log) {
    int d = blockIdx.x * 128 + threadIdx.x;
    int c = blockIdx.y;
    int b = blockIdx.z;

    float A2[NSTATE], h[NSTATE];
    #pragma unroll
    for (int n = 0; n < NSTATE; n++) {
        A2[n] = -__expf(A_log[d * NSTATE + n]) * 1.4426950408889634f;
        h[n] = 0.0f;
    }
    float sdl = 0.0f;
    int tbase = b * SEQL + c * CT;
    #pragma unroll 2
    for (int s = 0; s < CT; s++) {
        int t = tbase + s;
        float dl = g_delta[(size_t)t * DINNER + d];
        float xv = __bfloat162float(g_xcb[(size_t)t * DINNER + d]);
        float xd = xv * dl;
        sdl += dl;
        const float4* bc = (const float4*)(g_BC + (size_t)t * 32);
        float4 b0 = bc[0], b1 = bc[1], b2 = bc[2], b3 = bc[3];
        float bvals[NSTATE] = {b0.x,b0.y,b0.z,b0.w, b1.x,b1.y,b1.z,b1.w,
                               b2.x,b2.y,b2.z,b2.w, b3.x,b3.y,b3.z,b3.w};
        #pragma unroll
        for (int n = 0; n < NSTATE; n++) {
            float dA = exp2f(dl * A2[n]);
            h[n] = fmaf(dA, h[n], xd * bvals[n]);
        }
    }
    g_sdl[((size_t)b * NCH + c) * DINNER + d] = sdl;
    size_t base = (((size_t)b * NCH + c) * NSTATE) * DINNER + d;
    #pragma unroll
    for (int n = 0; n < NSTATE; n++)
        g_S[base + (size_t)n * DINNER] = h[n];
}

// ---------------------------------------------------------------------------
// Scan pass B: sequential carry; P recomputed from sum(delta).
// ---------------------------------------------------------------------------
__global__ void scan_phaseB(const float* __restrict__ A_log) {
    int idx = blockIdx.x * blockDim.x + threadIdx.x;
    if (idx >= BATCH * NSTATE * DINNER) return;
    int d = idx & 511;
    int n = (idx >> 9) & 15;
    int b = idx >> 13;
    float A2 = -__expf(A_log[d * NSTATE + n]) * 1.4426950408889634f;
    float h = 0.0f;
    for (int c = 0; c < NCH; c++) {
        size_t o = (((size_t)b * NCH + c) * NSTATE + n) * DINNER + d;
        g_H[o] = h;
        float P = exp2f(A2 * g_sdl[((size_t)b * NCH + c) * DINNER + d]);
        h = fmaf(P, h, g_S[o]);
    }
}

// ---------------------------------------------------------------------------
// Scan pass C: rerun chunk with true initial state; +x*D, *silu(z); bf16 out.
// ---------------------------------------------------------------------------
__global__ void scan_phaseC(const float* __restrict__ A_log,
                            const float* __restrict__ Dw) {
    int d = blockIdx.x * 128 + threadIdx.x;
    int c = blockIdx.y;
    int b = blockIdx.z;

    float A2[NSTATE], h[NSTATE];
    size_t hbase = (((size_t)b * NCH + c) * NSTATE) * DINNER + d;
    #pragma unroll
    for (int n = 0; n < NSTATE; n++) {
        A2[n] = -__expf(A_log[d * NSTATE + n]) * 1.4426950408889634f;
        h[n] = g_H[hbase + (size_t)n * DINNER];
    }
    float Dd = Dw[d];
    int tbase = b * SEQL + c * CT;
    #pragma unroll 2
    for (int s = 0; s < CT; s++) {
        int t = tbase + s;
        float dl = g_delta[(size_t)t * DINNER + d];
        float xv = __bfloat162float(g_xcb[(size_t)t * DINNER + d]);
        float xd = xv * dl;
        const float4* bc = (const float4*)(g_BC + (size_t)t * 32);
        float4 b0 = bc[0], b1 = bc[1], b2 = bc[2], b3 = bc[3];
        float4 c0 = bc[4], c1 = bc[5], c2 = bc[6], c3 = bc[7];
        float bvals[NSTATE] = {b0.x,b0.y,b0.z,b0.w, b1.x,b1.y,b1.z,b1.w,
                               b2.x,b2.y,b2.z,b2.w, b3.x,b3.y,b3.z,b3.w};
        float cvals[NSTATE] = {c0.x,c0.y,c0.z,c0.w, c1.x,c1.y,c1.z,c1.w,
                               c2.x,c2.y,c2.z,c2.w, c3.x,c3.y,c3.z,c3.w};
        float yv = 0.0f;
        #pragma unroll
        for (int n = 0; n < NSTATE; n++) {
            float dA = exp2f(dl * A2[n]);
            h[n] = fmaf(dA, h[n], xd * bvals[n]);
            yv = fmaf(h[n], cvals[n], yv);
        }
        float z = __bfloat162float(g_xzb[(size_t)t * (2 * DINNER) + DINNER + d]);
        g_yb[(size_t)t * DINNER + d] =
            __float2bfloat16((yv + xv * Dd) * silu_f(z));
    }
}

// ---------------------------------------------------------------------------
// Launch
// ---------------------------------------------------------------------------
extern "C" void kernel_launch(void* const* d_in, const int* in_sizes, int n_in,
                              void* d_out, int out_size) {
    const float* x          = (const float*)d_in[0];
    const float* norm_w     = (const float*)d_in[1];
    const float* in_proj_w  = (const float*)d_in[2];
    const float* conv_w     = (const float*)d_in[3];
    const float* conv_b     = (const float*)d_in[4];
    const float* A_log      = (const float*)d_in[5];
    const float* projB_w    = (const float*)d_in[6];
    const float* projC_w    = (const float*)d_in[7];
    const float* projDelta_w= (const float*)d_in[8];
    const float* projDelta_b= (const float*)d_in[9];
    const float* Dw         = (const float*)d_in[10];
    const float* out_proj_w = (const float*)d_in[11];
    float* out = (float*)d_out;

    __nv_bfloat16 *p_xnb, *p_xzb, *p_xcb, *p_winb, *p_wdbcb, *p_woutb, *p_yb;
    cudaGetSymbolAddress((void**)&p_xnb,   g_xnb);
    cudaGetSymbolAddress((void**)&p_xzb,   g_xzb);
    cudaGetSymbolAddress((void**)&p_xcb,   g_xcb);
    cudaGetSymbolAddress((void**)&p_winb,  g_Winb);
    cudaGetSymbolAddress((void**)&p_wdbcb, g_Wdbcb);
    cudaGetSymbolAddress((void**)&p_woutb, g_Woutb);
    cudaGetSymbolAddress((void**)&p_yb,    g_yb);

    cudaFuncSetAttribute(gemm_bf<0>, cudaFuncAttributeMaxDynamicSharedMemorySize, GSMEM);
    cudaFuncSetAttribute(gemm_bf<1>, cudaFuncAttributeMaxDynamicSharedMemorySize, GSMEM);
    cudaFuncSetAttribute(gemm_bf<2>, cudaFuncAttributeMaxDynamicSharedMemorySize, GSMEM);

    // 1. weight prep
    prep_w_kernel<<<(WIN_E + WDBC_E + WOUT_E + 255) / 256, 256>>>(
        in_proj_w, norm_w, projDelta_w, projB_w, projC_w, out_proj_w);

    // 2. RMSNorm -> bf16
    rmsnorm_kernel<<<NTOK, DMODEL>>>(x);

    // 3. in_proj: [8192,256]x[1024,256]^T -> g_xzb (bf16)
    gemm_bf<0><<<dim3(2 * DINNER / GBN, NTOK / GBM), 128, GSMEM>>>(
        p_xnb, p_winb, nullptr, p_xzb, NTOK, 2 * DINNER, DMODEL, nullptr, nullptr);

    // 4. causal conv + silu
    conv_silu_kernel<<<((NTOK / 4) * (DINNER / 2) + 255) / 256, 256>>>(conv_w, conv_b);

    // 5. delta/B/C projections: [8192,512]x[640,512]^T
    gemm_bf<1><<<dim3(NDBC / GBN, NTOK / GBM), 128, GSMEM>>>(
        p_xcb, p_wdbcb, nullptr, nullptr, NTOK, NDBC, DINNER, projDelta_b, nullptr);

    // 6-8. chunked selective scan
    scan_phaseA<<<dim3(DINNER / 128, NCH, BATCH), 128>>>(A_log);
    scan_phaseB<<<(BATCH * NSTATE * DINNER + 255) / 256, 256>>>(A_log);
    scan_phaseC<<<dim3(DINNER / 128, NCH, BATCH), 128>>>(A_log, Dw);

    // 9. out_proj + residual: [8192,512]x[256,512]^T + x
    gemm_bf<2><<<dim3(DMODEL / GBN, NTOK / GBM), 128, GSMEM>>>(
        p_yb, p_woutb, out, nullptr, NTOK, DMODEL, DINNER, nullptr, x);
}

// round 8
// speedup vs baseline: 3.6477x; 1.0713x over previous
#include <cuda_runtime.h>
#include <cuda_bf16.h>
#include <math.h>
#include <stdint.h>

// ---------------------------------------------------------------------------
// Problem constants
// ---------------------------------------------------------------------------
#define BATCH   4
#define SEQL    2048
#define DMODEL  256
#define DINNER  512
#define NSTATE  16
#define NTOK    (BATCH * SEQL)          // 8192
#define RMS_EPS 1.1920929e-07f

#define NCH     64                       // scan chunks
#define CT      (SEQL / NCH)             // 32 steps per chunk
#define NDBC    640                      // padded N for fused delta/B/C gemm

// ---------------------------------------------------------------------------
// Scratch (static device globals; no allocation allowed)
// ---------------------------------------------------------------------------
__device__ __nv_bfloat16 g_xnb  [(size_t)NTOK * DMODEL];      // rmsnorm (bf16)
__device__ __nv_bfloat16 g_xzb  [(size_t)NTOK * 2 * DINNER];  // x_branch|z bf16
__device__ __nv_bfloat16 g_xcb  [(size_t)NTOK * DINNER];      // conv+silu bf16
__device__ float         g_delta[(size_t)NTOK * DINNER];
__device__ float         g_BC   [(size_t)NTOK * 32];          // B(16) | C(16)
__device__ __nv_bfloat16 g_Winb [(size_t)(2 * DINNER) * DMODEL];
__device__ __nv_bfloat16 g_Wdbcb[(size_t)NDBC * DINNER];
__device__ __nv_bfloat16 g_Woutb[(size_t)DMODEL * DINNER];
__device__ __nv_bfloat16 g_yb   [(size_t)NTOK * DINNER];
__device__ float g_sdl[(size_t)BATCH * NCH * DINNER];          // per-chunk sum(delta)
__device__ float g_S  [(size_t)BATCH * NCH * NSTATE * DINNER];
__device__ float g_H  [(size_t)BATCH * NCH * NSTATE * DINNER];

// ---------------------------------------------------------------------------
// Helpers
// ---------------------------------------------------------------------------
__device__ __forceinline__ float ex2f(float x) {       // single MUFU.EX2
    float r;
    asm("ex2.approx.ftz.f32 %0, %1;" : "=f"(r) : "f"(x));
    return r;
}
__device__ __forceinline__ float silu_f(float v) { return v / (1.0f + __expf(-v)); }
__device__ __forceinline__ float softplus_f(float v) {
    return (v > 20.0f) ? v : __logf(1.0f + __expf(v));
}
__device__ __forceinline__ void mma_bf16(float (&d)[4], const uint32_t (&a)[4],
                                         const uint32_t (&b)[2]) {
    asm volatile(
        "mma.sync.aligned.m16n8k16.row.col.f32.bf16.bf16.f32 "
        "{%0,%1,%2,%3},{%4,%5,%6,%7},{%8,%9},{%0,%1,%2,%3};"
        : "+f"(d[0]), "+f"(d[1]), "+f"(d[2]), "+f"(d[3])
        : "r"(a[0]), "r"(a[1]), "r"(a[2]), "r"(a[3]), "r"(b[0]), "r"(b[1]));
}
#define LDSM_X4(r0, r1, r2, r3, addr)                                        \
    asm volatile("ldmatrix.sync.aligned.m8n8.x4.shared.b16 {%0,%1,%2,%3}, [%4];" \
                 : "=r"(r0), "=r"(r1), "=r"(r2), "=r"(r3) : "r"(addr))
#define CP_ASYNC16(dst, src) \
    asm volatile("cp.async.cg.shared.global [%0], [%1], 16;" :: "r"(dst), "l"(src))
#define CP_COMMIT() asm volatile("cp.async.commit_group;")

// ---------------------------------------------------------------------------
// Weight prep: bf16 conversions (+ norm_w folded into in_proj weights)
// ---------------------------------------------------------------------------
#define WIN_E  (2 * DINNER * DMODEL)    // 262144
#define WDBC_E (NDBC * DINNER)          // 327680
#define WOUT_E (DMODEL * DINNER)        // 131072
__global__ void prep_w_kernel(const float* __restrict__ win,
                              const float* __restrict__ normw,
                              const float* __restrict__ wd,
                              const float* __restrict__ wb,
                              const float* __restrict__ wc,
                              const float* __restrict__ wout) {
    int idx = blockIdx.x * blockDim.x + threadIdx.x;
    if (idx < WIN_E) {
        int k = idx & (DMODEL - 1);
        g_Winb[idx] = __float2bfloat16(win[idx] * normw[k]);
    }
    int j = idx - WIN_E;
    if (j >= 0 && j < WDBC_E) {
        int r = j / DINNER;
        int k = j - r * DINNER;
        float v;
        if      (r < 512) v = wd[(size_t)r * DINNER + k];
        else if (r < 528) v = wb[(size_t)(r - 512) * DINNER + k];
        else if (r < 544) v = wc[(size_t)(r - 528) * DINNER + k];
        else              v = 0.0f;
        g_Wdbcb[j] = __float2bfloat16(v);
    }
    int q = idx - WIN_E - WDBC_E;
    if (q >= 0 && q < WOUT_E) {
        g_Woutb[q] = __float2bfloat16(wout[q]);
    }
}

// ---------------------------------------------------------------------------
// RMSNorm -> bf16 (norm_w folded into weights)
// ---------------------------------------------------------------------------
__global__ void rmsnorm_kernel(const float* __restrict__ x) {
    int t = blockIdx.x;
    int i = threadIdx.x;
    float v = x[(size_t)t * DMODEL + i];
    float ss = v * v;
    #pragma unroll
    for (int o = 16; o; o >>= 1) ss += __shfl_xor_sync(0xFFFFFFFFu, ss, o);
    __shared__ float red[8];
    if ((i & 31) == 0) red[i >> 5] = ss;
    __syncthreads();
    float tot = 0.f;
    #pragma unroll
    for (int j = 0; j < 8; j++) tot += red[j];
    float scale = rsqrtf(tot * (1.0f / DMODEL) + RMS_EPS);
    g_xnb[(size_t)t * DMODEL + i] = __float2bfloat16(v * scale);
}

// ---------------------------------------------------------------------------
// bf16 tensor-core GEMM: C[M,N] = A[M,K](bf16) * W[N,K](bf16)^T, fp32 accum.
// CTA tile 128x64x32, 128 threads (4 warps), warp tile 64x32, ldmatrix,
// mma m16n8k16, 3-stage cp.async.
//  EPI 0: bf16 store (-> g_xzb)
//  EPI 1: n<512 softplus(v+bias)->g_delta; 512..543 -> g_BC
//  EPI 2: fp32 v + resid -> Cf (out_proj)
// ---------------------------------------------------------------------------
#define GBM 128
#define GBN 64
#define GBK 32
#define LDA 40                               // bf16 elems; 80B row stride
#define ATILE_B (GBM * LDA * 2)              // 10240
#define BTILE_B (GBN * LDA * 2)              // 5120
#define STAGE_B (ATILE_B + BTILE_B)          // 15360
#define GSMEM   (3 * STAGE_B)                // 46080

template<int EPI>
__global__ __launch_bounds__(128, 4)
void gemm_bf(const __nv_bfloat16* __restrict__ A,
             const __nv_bfloat16* __restrict__ W,
             float* __restrict__ Cf, __nv_bfloat16* __restrict__ Cb,
             int M, int N, int K,
             const float* __restrict__ bias,
             const float* __restrict__ resid) {
    extern __shared__ __align__(128) char dsm[];
    const uint32_t sbase = (uint32_t)__cvta_generic_to_shared(dsm);

    const int tid  = threadIdx.x;
    const int m0   = blockIdx.y * GBM;
    const int n0   = blockIdx.x * GBN;
    const int lane = tid & 31;
    const int wid  = tid >> 5;
    const int wm   = wid & 1;          // warp row (2)
    const int wn   = wid >> 1;         // warp col (2)
    const int g    = lane >> 2;        // 0..7
    const int t4   = lane & 3;         // 0..3

    float acc[4][4][4];
    #pragma unroll
    for (int mf = 0; mf < 4; mf++)
        #pragma unroll
        for (int nf = 0; nf < 4; nf++)
            #pragma unroll
            for (int r = 0; r < 4; r++) acc[mf][nf][r] = 0.0f;

    const uint32_t aoff =
        ((uint32_t)(wm * 64 + (lane & 15)) * LDA + ((lane >> 4) << 3)) * 2;
    const uint32_t boff =
        ((uint32_t)(wn * 32 + (lane & 7) + ((lane & 16) ? 8 : 0)) * LDA +
         (((lane >> 3) & 1) << 3)) * 2;

    auto issue = [&](int it) {
        const int stage = it % 3;
        const uint32_t ab = sbase + stage * STAGE_B;
        const uint32_t bb = ab + ATILE_B;
        const int k0 = it * GBK;
        #pragma unroll
        for (int i = 0; i < 6; i++) {
            int c    = tid + i * 128;
            int part = (c & 3) * 8;            // bf16 elems (16B chunk)
            if (c < 512) {
                int row = c >> 2;              // 0..127
                CP_ASYNC16(ab + (uint32_t)(row * LDA + part) * 2,
                           A + (size_t)(m0 + row) * K + k0 + part);
            } else {
                int row = (c - 512) >> 2;      // 0..63
                CP_ASYNC16(bb + (uint32_t)(row * LDA + part) * 2,
                           W + (size_t)(n0 + row) * K + k0 + part);
            }
        }
        CP_COMMIT();
    };

    const int niter = K / GBK;
    issue(0); issue(1);
    asm volatile("cp.async.wait_group 1;");
    __syncthreads();

    for (int it = 0; it < niter; it++) {
        if (it + 2 < niter) issue(it + 2);

        const int stage = it % 3;
        const uint32_t aA = sbase + stage * STAGE_B + aoff;
        const uint32_t aB = sbase + stage * STAGE_B + ATILE_B + boff;

        #pragma unroll
        for (int kc = 0; kc < 2; kc++) {
            uint32_t af[4][4], bf[4][2];
            #pragma unroll
            for (int mf = 0; mf < 4; mf++) {
                LDSM_X4(af[mf][0], af[mf][1], af[mf][2], af[mf][3],
                        aA + (uint32_t)(mf * 16 * LDA * 2 + kc * 32));
            }
            #pragma unroll
            for (int nfp = 0; nfp < 2; nfp++) {
                LDSM_X4(bf[2 * nfp][0], bf[2 * nfp][1],
                        bf[2 * nfp + 1][0], bf[2 * nfp + 1][1],
                        aB + (uint32_t)(nfp * 16 * LDA * 2 + kc * 32));
            }
            #pragma unroll
            for (int mf = 0; mf < 4; mf++)
                #pragma unroll
                for (int nf = 0; nf < 4; nf++)
                    mma_bf16(acc[mf][nf], af[mf], bf[nf]);
        }

        if (it + 1 < niter) {
            if (it + 2 < niter) asm volatile("cp.async.wait_group 1;");
            else                asm volatile("cp.async.wait_group 0;");
            __syncthreads();
        }
    }

    // Epilogue
    #pragma unroll
    for (int mf = 0; mf < 4; mf++) {
        #pragma unroll
        for (int nf = 0; nf < 4; nf++) {
            #pragma unroll
            for (int r = 0; r < 4; r++) {
                int t = m0 + wm * 64 + mf * 16 + g + ((r >> 1) ? 8 : 0);
                int n = n0 + wn * 32 + nf * 8 + t4 * 2 + (r & 1);
                float v = acc[mf][nf][r];
                if (EPI == 0) {
                    Cb[(size_t)t * N + n] = __float2bfloat16(v);
                } else if (EPI == 1) {
                    if (n < 512) {
                        g_delta[(size_t)t * DINNER + n] = softplus_f(v + bias[n]);
                    } else if (n < 544) {
                        g_BC[(size_t)t * 32 + (n - 512)] = v;
                    }
                } else { // EPI == 2
                    Cf[(size_t)t * N + n] = v + resid[(size_t)t * N + n];
                }
            }
        }
    }
}

// ---------------------------------------------------------------------------
// Causal depthwise conv (width 4) + bias + SiLU; bf16 in/out.
// Each thread: 2 adjacent channels x 4 timesteps (packed u32 loads/stores).
// ---------------------------------------------------------------------------
__global__ void conv_silu_kernel(const float* __restrict__ cw,
                                 const float* __restrict__ cb) {
    int q = blockIdx.x * blockDim.x + threadIdx.x;   // over (NTOK/4)*(DINNER/2)
    if (q >= (NTOK / 4) * (DINNER / 2)) return;
    int dp = (q & 255) * 2;                          // channel pair base
    int t0 = (q >> 8) * 4;
    int l0 = t0 & (SEQL - 1);
    float w0a = cw[dp * 4 + 0], w1a = cw[dp * 4 + 1];
    float w2a = cw[dp * 4 + 2], w3a = cw[dp * 4 + 3];
    float w0b = cw[dp * 4 + 4], w1b = cw[dp * 4 + 5];
    float w2b = cw[dp * 4 + 6], w3b = cw[dp * 4 + 7];
    float ba = cb[dp], bb = cb[dp + 1];
    float xa[7], xb[7];
    #pragma unroll
    for (int i = 0; i < 7; i++) {
        int li = l0 - 3 + i;
        if (li >= 0) {
            __nv_bfloat162 v = *(const __nv_bfloat162*)
                &g_xzb[(size_t)(t0 - 3 + i) * (2 * DINNER) + dp];
            xa[i] = __bfloat162float(v.x);
            xb[i] = __bfloat162float(v.y);
        } else { xa[i] = 0.0f; xb[i] = 0.0f; }
    }
    #pragma unroll
    for (int j = 0; j < 4; j++) {
        float va = fmaf(w3a, xa[j + 3], fmaf(w2a, xa[j + 2],
                   fmaf(w1a, xa[j + 1], fmaf(w0a, xa[j], ba))));
        float vb = fmaf(w3b, xb[j + 3], fmaf(w2b, xb[j + 2],
                   fmaf(w1b, xb[j + 1], fmaf(w0b, xb[j], bb))));
        __nv_bfloat162 o;
        o.x = __float2bfloat16(silu_f(va));
        o.y = __float2bfloat16(silu_f(vb));
        *(__nv_bfloat162*)&g_xcb[(size_t)(t0 + j) * DINNER + dp] = o;
    }
}

// ---------------------------------------------------------------------------
// Scan pass A: per-chunk end-state S and sum(delta).
// ---------------------------------------------------------------------------
__global__ void scan_phaseA(const float* __restrict__ A_log) {
    int d = blockIdx.x * 128 + threadIdx.x;
    int c = blockIdx.y;
    int b = blockIdx.z;

    float A2[NSTATE], h[NSTATE];
    #pragma unroll
    for (int n = 0; n < NSTATE; n++) {
        A2[n] = -__expf(A_log[d * NSTATE + n]) * 1.4426950408889634f;
        h[n] = 0.0f;
    }
    float sdl = 0.0f;
    int tbase = b * SEQL + c * CT;
    #pragma unroll 2
    for (int s = 0; s < CT; s++) {
        int t = tbase + s;
        float dl = g_delta[(size_t)t * DINNER + d];
        float xv = __bfloat162float(g_xcb[(size_t)t * DINNER + d]);
        float xd = xv * dl;
        sdl += dl;
        const float4* bc = (const float4*)(g_BC + (size_t)t * 32);
        float4 b0 = bc[0], b1 = bc[1], b2 = bc[2], b3 = bc[3];
        float bvals[NSTATE] = {b0.x,b0.y,b0.z,b0.w, b1.x,b1.y,b1.z,b1.w,
                               b2.x,b2.y,b2.z,b2.w, b3.x,b3.y,b3.z,b3.w};
        #pragma unroll
        for (int n = 0; n < NSTATE; n++) {
            float dA = ex2f(dl * A2[n]);
            h[n] = fmaf(dA, h[n], xd * bvals[n]);
        }
    }
    g_sdl[((size_t)b * NCH + c) * DINNER + d] = sdl;
    size_t base = (((size_t)b * NCH + c) * NSTATE) * DINNER + d;
    #pragma unroll
    for (int n = 0; n < NSTATE; n++)
        g_S[base + (size_t)n * DINNER] = h[n];
}

// ---------------------------------------------------------------------------
// Scan pass B: sequential carry; P recomputed from sum(delta).
// ---------------------------------------------------------------------------
__global__ void scan_phaseB(const float* __restrict__ A_log) {
    int idx = blockIdx.x * blockDim.x + threadIdx.x;
    if (idx >= BATCH * NSTATE * DINNER) return;
    int d = idx & 511;
    int n = (idx >> 9) & 15;
    int b = idx >> 13;
    float A2 = -__expf(A_log[d * NSTATE + n]) * 1.4426950408889634f;
    float h = 0.0f;
    for (int c = 0; c < NCH; c++) {
        size_t o = (((size_t)b * NCH + c) * NSTATE + n) * DINNER + d;
        g_H[o] = h;
        float P = ex2f(A2 * g_sdl[((size_t)b * NCH + c) * DINNER + d]);
        h = fmaf(P, h, g_S[o]);
    }
}

// ---------------------------------------------------------------------------
// Scan pass C: rerun chunk with true initial state; +x*D, *silu(z); bf16 out.
// ---------------------------------------------------------------------------
__global__ void scan_phaseC(const float* __restrict__ A_log,
                            const float* __restrict__ Dw) {
    int d = blockIdx.x * 128 + threadIdx.x;
    int c = blockIdx.y;
    int b = blockIdx.z;

    float A2[NSTATE], h[NSTATE];
    size_t hbase = (((size_t)b * NCH + c) * NSTATE) * DINNER + d;
    #pragma unroll
    for (int n = 0; n < NSTATE; n++) {
        A2[n] = -__expf(A_log[d * NSTATE + n]) * 1.4426950408889634f;
        h[n] = g_H[hbase + (size_t)n * DINNER];
    }
    float Dd = Dw[d];
    int tbase = b * SEQL + c * CT;
    #pragma unroll 2
    for (int s = 0; s < CT; s++) {
        int t = tbase + s;
        float dl = g_delta[(size_t)t * DINNER + d];
        float xv = __bfloat162float(g_xcb[(size_t)t * DINNER + d]);
        float xd = xv * dl;
        const float4* bc = (const float4*)(g_BC + (size_t)t * 32);
        float4 b0 = bc[0], b1 = bc[1], b2 = bc[2], b3 = bc[3];
        float4 c0 = bc[4], c1 = bc[5], c2 = bc[6], c3 = bc[7];
        float bvals[NSTATE] = {b0.x,b0.y,b0.z,b0.w, b1.x,b1.y,b1.z,b1.w,
                               b2.x,b2.y,b2.z,b2.w, b3.x,b3.y,b3.z,b3.w};
        float cvals[NSTATE] = {c0.x,c0.y,c0.z,c0.w, c1.x,c1.y,c1.z,c1.w,
                               c2.x,c2.y,c2.z,c2.w, c3.x,c3.y,c3.z,c3.w};
        float yv = 0.0f;
        #pragma unroll
        for (int n = 0; n < NSTATE; n++) {
            float dA = ex2f(dl * A2[n]);
            h[n] = fmaf(dA, h[n], xd * bvals[n]);
            yv = fmaf(h[n], cvals[n], yv);
        }
        float z = __bfloat162float(g_xzb[(size_t)t * (2 * DINNER) + DINNER + d]);
        g_yb[(size_t)t * DINNER + d] =
            __float2bfloat16((yv + xv * Dd) * silu_f(z));
    }
}

// ---------------------------------------------------------------------------
// Launch
// ---------------------------------------------------------------------------
extern "C" void kernel_launch(void* const* d_in, const int* in_sizes, int n_in,
                              void* d_out, int out_size) {
    const float* x          = (const float*)d_in[0];
    const float* norm_w     = (const float*)d_in[1];
    const float* in_proj_w  = (const float*)d_in[2];
    const float* conv_w     = (const float*)d_in[3];
    const float* conv_b     = (const float*)d_in[4];
    const float* A_log      = (const float*)d_in[5];
    const float* projB_w    = (const float*)d_in[6];
    const float* projC_w    = (const float*)d_in[7];
    const float* projDelta_w= (const float*)d_in[8];
    const float* projDelta_b= (const float*)d_in[9];
    const float* Dw         = (const float*)d_in[10];
    const float* out_proj_w = (const float*)d_in[11];
    float* out = (float*)d_out;

    __nv_bfloat16 *p_xnb, *p_xzb, *p_xcb, *p_winb, *p_wdbcb, *p_woutb, *p_yb;
    cudaGetSymbolAddress((void**)&p_xnb,   g_xnb);
    cudaGetSymbolAddress((void**)&p_xzb,   g_xzb);
    cudaGetSymbolAddress((void**)&p_xcb,   g_xcb);
    cudaGetSymbolAddress((void**)&p_winb,  g_Winb);
    cudaGetSymbolAddress((void**)&p_wdbcb, g_Wdbcb);
    cudaGetSymbolAddress((void**)&p_woutb, g_Woutb);
    cudaGetSymbolAddress((void**)&p_yb,    g_yb);

    cudaFuncSetAttribute(gemm_bf<0>, cudaFuncAttributeMaxDynamicSharedMemorySize, GSMEM);
    cudaFuncSetAttribute(gemm_bf<1>, cudaFuncAttributeMaxDynamicSharedMemorySize, GSMEM);
    cudaFuncSetAttribute(gemm_bf<2>, cudaFuncAttributeMaxDynamicSharedMemorySize, GSMEM);

    // 1. weight prep
    prep_w_kernel<<<(WIN_E + WDBC_E + WOUT_E + 255) / 256, 256>>>(
        in_proj_w, norm_w, projDelta_w, projB_w, projC_w, out_proj_w);

    // 2. RMSNorm -> bf16
    rmsnorm_kernel<<<NTOK, DMODEL>>>(x);

    // 3. in_proj: [8192,256]x[1024,256]^T -> g_xzb (bf16)
    gemm_bf<0><<<dim3(2 * DINNER / GBN, NTOK / GBM), 128, GSMEM>>>(
        p_xnb, p_winb, nullptr, p_xzb, NTOK, 2 * DINNER, DMODEL, nullptr, nullptr);

    // 4. causal conv + silu
    conv_silu_kernel<<<((NTOK / 4) * (DINNER / 2) + 255) / 256, 256>>>(conv_w, conv_b);

    // 5. delta/B/C projections: [8192,512]x[640,512]^T
    gemm_bf<1><<<dim3(NDBC / GBN, NTOK / GBM), 128, GSMEM>>>(
        p_xcb, p_wdbcb, nullptr, nullptr, NTOK, NDBC, DINNER, projDelta_b, nullptr);

    // 6-8. chunked selective scan
    scan_phaseA<<<dim3(DINNER / 128, NCH, BATCH), 128>>>(A_log);
    scan_phaseB<<<(BATCH * NSTATE * DINNER + 255) / 256, 256>>>(A_log);
    scan_phaseC<<<dim3(DINNER / 128, NCH, BATCH), 128>>>(A_log, Dw);

    // 9. out_proj + residual: [8192,512]x[256,512]^T + x
    gemm_bf<2><<<dim3(DMODEL / GBN, NTOK / GBM), 128, GSMEM>>>(
        p_yb, p_woutb, out, nullptr, NTOK, DMODEL, DINNER, nullptr, x);
}